// round 5
// baseline (speedup 1.0000x reference)
#include <cuda_runtime.h>
#include <cuda_fp16.h>

// Fixed problem shapes
#define NROIS 1024
#define CCH   512
#define HH    38
#define WW    50
#define HWSZ  (HH * WW)          // 1900
#define PRE   14                 // pooling_size * 2
#define PS    7

#define THREADS  256
#define NWARPS   (THREADS / 32)
#define SOUT_PAD 516             // 129 groups of 4 floats; bank shift of 4 per row

// Transposed feature map in fp16: [cell = y*W + x][channel], 1.94 MB (L2-resident).
__device__ __align__(16) __half g_trh[HWSZ * CCH];

// ---------------- transpose+convert kernel: [C][H*W] fp32 -> [H*W][C] fp16 ----------------
__global__ __launch_bounds__(256)
void transpose_kernel(const float* __restrict__ bottom)
{
    __shared__ float t[32][33];
    const int c0 = blockIdx.x * 32;     // cell tile base
    const int h0 = blockIdx.y * 32;     // channel tile base
    const int tx = threadIdx.x;         // 0..31
    const int ty = threadIdx.y;         // 0..7

#pragma unroll
    for (int i = 0; i < 4; i++) {
        int ch = h0 + ty + i * 8;
        int cc = c0 + tx;
        t[ty + i * 8][tx] = (cc < HWSZ) ? bottom[ch * HWSZ + cc] : 0.0f;
    }
    __syncthreads();
#pragma unroll
    for (int i = 0; i < 4; i++) {
        int cc = c0 + ty + i * 8;
        int ch = h0 + tx;
        if (cc < HWSZ) g_trh[cc * CCH + ch] = __float2half(t[tx][ty + i * 8]);
    }
}

// ---------------- main kernel: one CTA per ROI ----------------
__device__ __forceinline__ float grid_coord(float lo, float hi, float L, int j) {
    float t0 = (hi - lo) / L;
    float t2 = (lo + hi - L) / L;
    float base = -1.0f + (float)j * (2.0f / 13.0f);
    float g = t0 * base + t2;
    return (g + 1.0f) * 0.5f * L;
}

__device__ __forceinline__ __half2 u2h(unsigned u) { return *(__half2*)&u; }

__global__ __launch_bounds__(THREADS)
void crop_pool_kernel(const float* __restrict__ rois,
                      float* __restrict__ out)
{
    __shared__ int   sxi[2][PRE];  __shared__ float sxw[2][PRE];
    __shared__ int   syi[2][PRE];  __shared__ float syw[2][PRE];
    __shared__ int4  soff[PRE * PRE];    // per-sample 4 corner offsets (half elements)
    __shared__ uint4 swth[PRE * PRE];    // per-sample 4 weights as broadcast half2
    __shared__ __align__(16) float sout[14 * SOUT_PAD];

    const int roi = blockIdx.x;
    const int tid = threadIdx.x;

    // ---- Phase 1: per-axis corner indices + weights (threads 0..27) ----
    if (tid < 2 * PRE) {
        const int isY = (tid >= PRE);
        const int j   = isY ? (tid - PRE) : tid;
        const float lo = rois[roi * 5 + (isY ? 2 : 1)] * (1.0f / 16.0f);
        const float hi = rois[roi * 5 + (isY ? 4 : 3)] * (1.0f / 16.0f);
        const float Lf = isY ? (float)(HH - 1) : (float)(WW - 1);
        const int   Li = isY ? (HH - 1) : (WW - 1);

        float ic = grid_coord(lo, hi, Lf, j);
        float f  = floorf(ic);
        float a  = ic - f;
        int i0 = (int)f;
        int i1 = i0 + 1;
        int i0c = min(max(i0, 0), Li);
        int i1c = min(max(i1, 0), Li);
        float w0 = (i0 >= 0 && i0 <= Li) ? (1.0f - a) : 0.0f;
        float w1 = (i1 >= 0 && i1 <= Li) ? a : 0.0f;

        if (!isY) {
            sxi[0][j] = i0c; sxi[1][j] = i1c; sxw[0][j] = w0; sxw[1][j] = w1;
        } else {
            syi[0][j] = i0c; syi[1][j] = i1c; syw[0][j] = w0; syw[1][j] = w1;
        }
    }
    __syncthreads();

    // ---- Phase 2: per-sample packed corner offsets + half2 weights (threads 0..195) ----
    if (tid < PRE * PRE) {
        const int jy = tid / PRE;
        const int jx = tid - jy * PRE;
        const int y0 = syi[0][jy], y1 = syi[1][jy];
        const int x0 = sxi[0][jx], x1 = sxi[1][jx];
        const float wy0 = syw[0][jy], wy1 = syw[1][jy];
        const float wx0 = sxw[0][jx], wx1 = sxw[1][jx];
        int4 o;
        o.x = (y0 * WW + x0) * CCH;
        o.y = (y0 * WW + x1) * CCH;
        o.z = (y1 * WW + x0) * CCH;
        o.w = (y1 * WW + x1) * CCH;
        uint4 w;
        __half2 h0 = __float2half2_rn(wy0 * wx0);
        __half2 h1 = __float2half2_rn(wy0 * wx1);
        __half2 h2 = __float2half2_rn(wy1 * wx0);
        __half2 h3 = __float2half2_rn(wy1 * wx1);
        w.x = *(unsigned*)&h0;
        w.y = *(unsigned*)&h1;
        w.z = *(unsigned*)&h2;
        w.w = *(unsigned*)&h3;
        soff[tid] = o;
        swth[tid] = w;
    }
    __syncthreads();

    const int warp = tid >> 5;
    const int lane = tid & 31;
    const __half* __restrict__ trp = g_trh;

    // ---- Main loop: 4 chunks of pooled rows {0,1},{2,3},{4,5},{6} ----
    for (int pp = 0; pp < 4; pp++) {
        const int nwin  = (pp < 3) ? 14 : 7;     // windows in this chunk
        const int ntask = nwin * 2;              // x 2 channel blocks of 256

        for (int t = warp; t < ntask; t += NWARPS) {
            int win, chblk;
            if (pp < 3) { chblk = t / 14; win = t - chblk * 14; }
            else        { chblk = t / 7;  win = t - chblk * 7;  }
            const int py = pp * 2 + (win >= 7 ? 1 : 0);
            const int px = (win >= 7) ? (win - 7) : win;
            const int s00 = (2 * py) * PRE + 2 * px;
            const int choff = chblk * 256 + lane * 8;   // half-element offset, 8 ch/lane

            __half2 m2[4];
#pragma unroll
            for (int s = 0; s < 4; s++) {
                const int sid = s00 + (s >> 1) * PRE + (s & 1);
                const int4  o  = soff[sid];
                const uint4 wh = swth[sid];
                const __half2 w0 = u2h(wh.x), w1 = u2h(wh.y);
                const __half2 w2 = u2h(wh.z), w3 = u2h(wh.w);
                uint4 c0 = __ldg((const uint4*)(trp + o.x + choff));
                uint4 c1 = __ldg((const uint4*)(trp + o.y + choff));
                uint4 c2 = __ldg((const uint4*)(trp + o.z + choff));
                uint4 c3 = __ldg((const uint4*)(trp + o.w + choff));
                const unsigned* u0 = (const unsigned*)&c0;
                const unsigned* u1 = (const unsigned*)&c1;
                const unsigned* u2p = (const unsigned*)&c2;
                const unsigned* u3 = (const unsigned*)&c3;
#pragma unroll
                for (int k = 0; k < 4; k++) {
                    __half2 acc = __hmul2(w0, u2h(u0[k]));
                    acc = __hfma2(w1, u2h(u1[k]), acc);
                    acc = __hfma2(w2, u2h(u2p[k]), acc);
                    acc = __hfma2(w3, u2h(u3[k]), acc);
                    m2[k] = (s == 0) ? acc : __hmax2(m2[k], acc);
                }
            }

            // convert to fp32 and stage with rotational swizzle:
            // group g = ch>>2 stored at ((g + 4*win) & 127)
            const int g0 = choff >> 2;            // lane's first 4-ch group
            const int base = win * SOUT_PAD;
            float2 fa = __half22float2(m2[0]);
            float2 fb = __half22float2(m2[1]);
            float2 fc = __half22float2(m2[2]);
            float2 fd = __half22float2(m2[3]);
            int gg0 = (g0 + 4 * win) & 127;
            int gg1 = (g0 + 1 + 4 * win) & 127;
            *(float4*)(&sout[base + gg0 * 4]) = make_float4(fa.x, fa.y, fb.x, fb.y);
            *(float4*)(&sout[base + gg1 * 4]) = make_float4(fc.x, fc.y, fd.x, fd.y);
        }
        __syncthreads();

        // ---- coalesced output: 56B-contiguous runs per channel, swizzled LDS reads ----
        float* ob = out + (size_t)roi * (CCH * PS * PS) + pp * 14;
        const int ne = nwin * CCH;
        if (pp < 3) {
            for (int e = tid; e < ne; e += THREADS) {
                int ch = e / 14;
                int o  = e - ch * 14;
                int gg = ((ch >> 2) + 4 * o) & 127;
                ob[ch * 49 + o] = sout[o * SOUT_PAD + gg * 4 + (ch & 3)];
            }
        } else {
            for (int e = tid; e < ne; e += THREADS) {
                int ch = e / 7;
                int o  = e - ch * 7;
                int gg = ((ch >> 2) + 4 * o) & 127;
                ob[ch * 49 + o] = sout[o * SOUT_PAD + gg * 4 + (ch & 3)];
            }
        }
        __syncthreads();
    }
}

extern "C" void kernel_launch(void* const* d_in, const int* in_sizes, int n_in,
                              void* d_out, int out_size)
{
    const float* bottom = (const float*)d_in[0];
    const float* rois   = (const float*)d_in[1];
    float* out = (float*)d_out;

    dim3 tgrid((HWSZ + 31) / 32, CCH / 32);
    transpose_kernel<<<tgrid, dim3(32, 8)>>>(bottom);
    crop_pool_kernel<<<NROIS, THREADS>>>(rois, out);
}

// round 7
// speedup vs baseline: 1.0271x; 1.0271x over previous
#include <cuda_runtime.h>
#include <cuda_fp16.h>

// Fixed problem shapes
#define NROIS 1024
#define CCH   512
#define HH    38
#define WW    50
#define HWSZ  (HH * WW)          // 1900
#define PRE   14                 // pooling_size * 2
#define PS    7

#define THREADS  256
#define NWARPS   (THREADS / 32)
#define SOUT_PAD 516             // linear layout: ~2-way LDS conflicts max

// Transposed feature map in fp16: [cell = y*W + x][channel], 1.94 MB (L2-resident).
__device__ __align__(16) __half g_trh[HWSZ * CCH];

// ---------------- transpose+convert kernel: [C][H*W] fp32 -> [H*W][C] fp16 ----------------
__global__ __launch_bounds__(256)
void transpose_kernel(const float* __restrict__ bottom)
{
    __shared__ float t[32][33];
    const int c0 = blockIdx.x * 32;     // cell tile base
    const int h0 = blockIdx.y * 32;     // channel tile base
    const int tx = threadIdx.x;         // 0..31
    const int ty = threadIdx.y;         // 0..7

#pragma unroll
    for (int i = 0; i < 4; i++) {
        int ch = h0 + ty + i * 8;
        int cc = c0 + tx;
        t[ty + i * 8][tx] = (cc < HWSZ) ? bottom[ch * HWSZ + cc] : 0.0f;
    }
    __syncthreads();
#pragma unroll
    for (int i = 0; i < 4; i++) {
        int cc = c0 + ty + i * 8;
        int ch = h0 + tx;
        if (cc < HWSZ) g_trh[cc * CCH + ch] = __float2half(t[tx][ty + i * 8]);
    }
}

// ---------------- main kernel: one CTA per ROI ----------------
__device__ __forceinline__ float grid_coord(float lo, float hi, float L, int j) {
    float t0 = (hi - lo) / L;
    float t2 = (lo + hi - L) / L;
    float base = -1.0f + (float)j * (2.0f / 13.0f);
    float g = t0 * base + t2;
    return (g + 1.0f) * 0.5f * L;
}

__device__ __forceinline__ __half2 u2h(unsigned u) { return *(__half2*)&u; }

__global__ __launch_bounds__(THREADS)
void crop_pool_kernel(const float* __restrict__ rois,
                      float* __restrict__ out)
{
    __shared__ int   sxi[2][PRE];  __shared__ float sxw[2][PRE];
    __shared__ int   syi[2][PRE];  __shared__ float syw[2][PRE];
    __shared__ int4  soff[PRE * PRE];    // per-sample 4 corner offsets (half elements)
    __shared__ uint4 swth[PRE * PRE];    // per-sample 4 weights as broadcast half2
    __shared__ __align__(16) float sout[14 * SOUT_PAD];

    const int roi = blockIdx.x;
    const int tid = threadIdx.x;

    // ---- Phase 1: per-axis corner indices + weights (threads 0..27) ----
    if (tid < 2 * PRE) {
        const int isY = (tid >= PRE);
        const int j   = isY ? (tid - PRE) : tid;
        const float lo = rois[roi * 5 + (isY ? 2 : 1)] * (1.0f / 16.0f);
        const float hi = rois[roi * 5 + (isY ? 4 : 3)] * (1.0f / 16.0f);
        const float Lf = isY ? (float)(HH - 1) : (float)(WW - 1);
        const int   Li = isY ? (HH - 1) : (WW - 1);

        float ic = grid_coord(lo, hi, Lf, j);
        float f  = floorf(ic);
        float a  = ic - f;
        int i0 = (int)f;
        int i1 = i0 + 1;
        int i0c = min(max(i0, 0), Li);
        int i1c = min(max(i1, 0), Li);
        float w0 = (i0 >= 0 && i0 <= Li) ? (1.0f - a) : 0.0f;
        float w1 = (i1 >= 0 && i1 <= Li) ? a : 0.0f;

        if (!isY) {
            sxi[0][j] = i0c; sxi[1][j] = i1c; sxw[0][j] = w0; sxw[1][j] = w1;
        } else {
            syi[0][j] = i0c; syi[1][j] = i1c; syw[0][j] = w0; syw[1][j] = w1;
        }
    }
    __syncthreads();

    // ---- Phase 2: per-sample packed corner offsets + half2 weights (threads 0..195) ----
    if (tid < PRE * PRE) {
        const int jy = tid / PRE;
        const int jx = tid - jy * PRE;
        const int y0 = syi[0][jy], y1 = syi[1][jy];
        const int x0 = sxi[0][jx], x1 = sxi[1][jx];
        const float wy0 = syw[0][jy], wy1 = syw[1][jy];
        const float wx0 = sxw[0][jx], wx1 = sxw[1][jx];
        int4 o;
        o.x = (y0 * WW + x0) * CCH;
        o.y = (y0 * WW + x1) * CCH;
        o.z = (y1 * WW + x0) * CCH;
        o.w = (y1 * WW + x1) * CCH;
        uint4 w;
        __half2 h0 = __float2half2_rn(wy0 * wx0);
        __half2 h1 = __float2half2_rn(wy0 * wx1);
        __half2 h2 = __float2half2_rn(wy1 * wx0);
        __half2 h3 = __float2half2_rn(wy1 * wx1);
        w.x = *(unsigned*)&h0;
        w.y = *(unsigned*)&h1;
        w.z = *(unsigned*)&h2;
        w.w = *(unsigned*)&h3;
        soff[tid] = o;
        swth[tid] = w;
    }
    __syncthreads();

    const int warp = tid >> 5;
    const int lane = tid & 31;
    const __half* __restrict__ trp = g_trh;

    // copy-loop lane mappings (fixed per thread, no division)
    // full chunks (14 windows): 2 channels/warp-row, lanes split 16/16, 32 iters
    const int oA    = lane & 15;
    const int chA   = 2 * warp + (lane >> 4);
    const bool actA = (oA < 14);
    // last chunk (7 windows): 4 channels/warp-row, lanes split 8/8/8/8, 16 iters
    const int oB    = lane & 7;
    const int chB   = 4 * warp + (lane >> 3);
    const bool actB = (oB < 7);

    // ---- Main loop: 4 chunks of pooled rows {0,1},{2,3},{4,5},{6} ----
    for (int pp = 0; pp < 4; pp++) {
        const int nwin  = (pp < 3) ? 14 : 7;     // windows in this chunk
        const int ntask = nwin * 2;              // x 2 channel blocks of 256

        for (int t = warp; t < ntask; t += NWARPS) {
            int win, chblk;
            if (pp < 3) { chblk = t / 14; win = t - chblk * 14; }
            else        { chblk = t / 7;  win = t - chblk * 7;  }
            const int py = pp * 2 + (win >= 7 ? 1 : 0);
            const int px = (win >= 7) ? (win - 7) : win;
            const int s00 = (2 * py) * PRE + 2 * px;
            const int choff = chblk * 256 + lane * 8;   // half-element offset, 8 ch/lane

            __half2 m2[4];
#pragma unroll
            for (int s = 0; s < 4; s++) {
                const int sid = s00 + (s >> 1) * PRE + (s & 1);
                const int4  o  = soff[sid];
                const uint4 wh = swth[sid];
                const __half2 w0 = u2h(wh.x), w1 = u2h(wh.y);
                const __half2 w2 = u2h(wh.z), w3 = u2h(wh.w);
                uint4 c0 = __ldg((const uint4*)(trp + o.x + choff));
                uint4 c1 = __ldg((const uint4*)(trp + o.y + choff));
                uint4 c2 = __ldg((const uint4*)(trp + o.z + choff));
                uint4 c3 = __ldg((const uint4*)(trp + o.w + choff));
                const unsigned* u0  = (const unsigned*)&c0;
                const unsigned* u1  = (const unsigned*)&c1;
                const unsigned* u2p = (const unsigned*)&c2;
                const unsigned* u3  = (const unsigned*)&c3;
#pragma unroll
                for (int k = 0; k < 4; k++) {
                    __half2 acc = __hmul2(w0, u2h(u0[k]));
                    acc = __hfma2(w1, u2h(u1[k]), acc);
                    acc = __hfma2(w2, u2h(u2p[k]), acc);
                    acc = __hfma2(w3, u2h(u3[k]), acc);
                    m2[k] = (s == 0) ? acc : __hmax2(m2[k], acc);
                }
            }

            // convert to fp32, stage linearly: sout[win][ch]
            float2 fa = __half22float2(m2[0]);
            float2 fb = __half22float2(m2[1]);
            float2 fc = __half22float2(m2[2]);
            float2 fd = __half22float2(m2[3]);
            float* sp = &sout[win * SOUT_PAD + choff];
            *(float4*)(sp)     = make_float4(fa.x, fa.y, fb.x, fb.y);
            *(float4*)(sp + 4) = make_float4(fc.x, fc.y, fd.x, fd.y);
        }
        __syncthreads();

        // ---- coalesced output copy, zero per-iter index math ----
        float* ob = out + (size_t)roi * (CCH * PS * PS) + pp * 14;
        if (pp < 3) {
            const float* sp = &sout[oA * SOUT_PAD + chA];
            float*       op = &ob[chA * 49 + oA];
#pragma unroll 8
            for (int it = 0; it < 32; it++) {       // 32 x 16ch steps -> 512 channels
                if (actA) *op = *sp;
                sp += 16;           // +16 channels
                op += 16 * 49;
            }
        } else {
            const float* sp = &sout[oB * SOUT_PAD + chB];
            float*       op = &ob[chB * 49 + oB];
#pragma unroll 8
            for (int it = 0; it < 16; it++) {       // 16 x 32ch steps -> 512 channels
                if (actB) *op = *sp;
                sp += 32;           // +32 channels
                op += 32 * 49;
            }
        }
        __syncthreads();
    }
}

extern "C" void kernel_launch(void* const* d_in, const int* in_sizes, int n_in,
                              void* d_out, int out_size)
{
    const float* bottom = (const float*)d_in[0];
    const float* rois   = (const float*)d_in[1];
    float* out = (float*)d_out;

    dim3 tgrid((HWSZ + 31) / 32, CCH / 32);
    transpose_kernel<<<tgrid, dim3(32, 8)>>>(bottom);
    crop_pool_kernel<<<NROIS, THREADS>>>(rois, out);
}

// round 8
// speedup vs baseline: 1.2153x; 1.1832x over previous
#include <cuda_runtime.h>
#include <cuda_fp16.h>

// Fixed problem shapes
#define NROIS 1024
#define CCH   512
#define HH    38
#define WW    50
#define HWSZ  (HH * WW)          // 1900
#define PRE   14                 // pooling_size * 2
#define PS    7

#define THREADS  256
#define NWARPS   (THREADS / 32)
#define NTASKS   98              // 49 windows x 2 channel-blocks of 256
#define SOUT_PAD 520             // halves per window row: 1040B (16B-aligned), 2-way LDS max

// Transposed feature map in fp16: [cell = y*W + x][channel], 1.94 MB (L2-resident).
__device__ __align__(16) __half g_trh[HWSZ * CCH];

// ---------------- transpose+convert kernel: [C][H*W] fp32 -> [H*W][C] fp16 ----------------
__global__ __launch_bounds__(256)
void transpose_kernel(const float* __restrict__ bottom)
{
    __shared__ float t[32][33];
    const int c0 = blockIdx.x * 32;     // cell tile base
    const int h0 = blockIdx.y * 32;     // channel tile base
    const int tx = threadIdx.x;         // 0..31
    const int ty = threadIdx.y;         // 0..7

#pragma unroll
    for (int i = 0; i < 4; i++) {
        int ch = h0 + ty + i * 8;
        int cc = c0 + tx;
        t[ty + i * 8][tx] = (cc < HWSZ) ? bottom[ch * HWSZ + cc] : 0.0f;
    }
    __syncthreads();
#pragma unroll
    for (int i = 0; i < 4; i++) {
        int cc = c0 + ty + i * 8;
        int ch = h0 + tx;
        if (cc < HWSZ) g_trh[cc * CCH + ch] = __float2half(t[tx][ty + i * 8]);
    }
}

// ---------------- main kernel: one CTA per ROI ----------------
__device__ __forceinline__ float grid_coord(float lo, float hi, float L, int j) {
    float t0 = (hi - lo) / L;
    float t2 = (lo + hi - L) / L;
    float base = -1.0f + (float)j * (2.0f / 13.0f);
    float g = t0 * base + t2;
    return (g + 1.0f) * 0.5f * L;
}

__device__ __forceinline__ __half2 u2h(unsigned u) { return *(__half2*)&u; }

__global__ __launch_bounds__(THREADS)
void crop_pool_kernel(const float* __restrict__ rois,
                      float* __restrict__ out)
{
    __shared__ int   sxi[2][PRE];  __shared__ float sxw[2][PRE];
    __shared__ int   syi[2][PRE];  __shared__ float syw[2][PRE];
    __shared__ int4  soff[PRE * PRE];     // per-sample 4 corner offsets (half elements)
    __shared__ uint4 swth[PRE * PRE];     // per-sample 4 weights as broadcast half2
    __shared__ short s00tab[49];          // window -> first sample id
    __shared__ __align__(16) __half sout_h[49 * SOUT_PAD];   // full-ROI staging (~51KB)

    const int roi = blockIdx.x;
    const int tid = threadIdx.x;

    // ---- Phase 1: per-axis corner indices + weights (threads 0..27) ----
    if (tid < 2 * PRE) {
        const int isY = (tid >= PRE);
        const int j   = isY ? (tid - PRE) : tid;
        const float lo = rois[roi * 5 + (isY ? 2 : 1)] * (1.0f / 16.0f);
        const float hi = rois[roi * 5 + (isY ? 4 : 3)] * (1.0f / 16.0f);
        const float Lf = isY ? (float)(HH - 1) : (float)(WW - 1);
        const int   Li = isY ? (HH - 1) : (WW - 1);

        float ic = grid_coord(lo, hi, Lf, j);
        float f  = floorf(ic);
        float a  = ic - f;
        int i0 = (int)f;
        int i1 = i0 + 1;
        int i0c = min(max(i0, 0), Li);
        int i1c = min(max(i1, 0), Li);
        float w0 = (i0 >= 0 && i0 <= Li) ? (1.0f - a) : 0.0f;
        float w1 = (i1 >= 0 && i1 <= Li) ? a : 0.0f;

        if (!isY) {
            sxi[0][j] = i0c; sxi[1][j] = i1c; sxw[0][j] = w0; sxw[1][j] = w1;
        } else {
            syi[0][j] = i0c; syi[1][j] = i1c; syw[0][j] = w0; syw[1][j] = w1;
        }
    }
    // window -> s00 lookup (threads 32..80)
    if (tid >= 32 && tid < 32 + 49) {
        int win = tid - 32;
        int py = win / 7;
        int px = win - py * 7;
        s00tab[win] = (short)((2 * py) * PRE + 2 * px);
    }
    __syncthreads();

    // ---- Phase 2: per-sample packed corner offsets + half2 weights (threads 0..195) ----
    if (tid < PRE * PRE) {
        const int jy = tid / PRE;
        const int jx = tid - jy * PRE;
        const int y0 = syi[0][jy], y1 = syi[1][jy];
        const int x0 = sxi[0][jx], x1 = sxi[1][jx];
        const float wy0 = syw[0][jy], wy1 = syw[1][jy];
        const float wx0 = sxw[0][jx], wx1 = sxw[1][jx];
        int4 o;
        o.x = (y0 * WW + x0) * CCH;
        o.y = (y0 * WW + x1) * CCH;
        o.z = (y1 * WW + x0) * CCH;
        o.w = (y1 * WW + x1) * CCH;
        uint4 w;
        __half2 h0 = __float2half2_rn(wy0 * wx0);
        __half2 h1 = __float2half2_rn(wy0 * wx1);
        __half2 h2 = __float2half2_rn(wy1 * wx0);
        __half2 h3 = __float2half2_rn(wy1 * wx1);
        w.x = *(unsigned*)&h0;
        w.y = *(unsigned*)&h1;
        w.z = *(unsigned*)&h2;
        w.w = *(unsigned*)&h3;
        soff[tid] = o;
        swth[tid] = w;
    }
    __syncthreads();

    const int warp = tid >> 5;
    const int lane = tid & 31;
    const __half* __restrict__ trp = g_trh;

    // ---- Compute phase: all 98 tasks, no intermediate barriers ----
    for (int t = warp; t < NTASKS; t += NWARPS) {
        const int win   = t >> 1;
        const int chblk = t & 1;
        const int s00   = s00tab[win];
        const int choff = chblk * 256 + lane * 8;   // half-element offset, 8 ch/lane

        __half2 m2[4];
#pragma unroll
        for (int s = 0; s < 4; s++) {
            const int sid = s00 + (s >> 1) * PRE + (s & 1);
            const int4  o  = soff[sid];
            const uint4 wh = swth[sid];
            const __half2 w0 = u2h(wh.x), w1 = u2h(wh.y);
            const __half2 w2 = u2h(wh.z), w3 = u2h(wh.w);
            uint4 c0 = __ldg((const uint4*)(trp + o.x + choff));
            uint4 c1 = __ldg((const uint4*)(trp + o.y + choff));
            uint4 c2 = __ldg((const uint4*)(trp + o.z + choff));
            uint4 c3 = __ldg((const uint4*)(trp + o.w + choff));
            const unsigned* u0  = (const unsigned*)&c0;
            const unsigned* u1  = (const unsigned*)&c1;
            const unsigned* u2p = (const unsigned*)&c2;
            const unsigned* u3  = (const unsigned*)&c3;
#pragma unroll
            for (int k = 0; k < 4; k++) {
                __half2 acc = __hmul2(w0, u2h(u0[k]));
                acc = __hfma2(w1, u2h(u1[k]), acc);
                acc = __hfma2(w2, u2h(u2p[k]), acc);
                acc = __hfma2(w3, u2h(u3[k]), acc);
                m2[k] = (s == 0) ? acc : __hmax2(m2[k], acc);
            }
        }
        // store raw half results: 16B per lane, banks 0..31 conflict-free
        *(uint4*)(&sout_h[win * SOUT_PAD + choff]) = *(uint4*)m2;
    }
    __syncthreads();

    // ---- Copy phase: half -> float, coalesced output ----
    // warp handles channel pair (c, c+1); lanes 0-15 -> c, 16-31 -> c+1; oA = lane&15
    const int oA  = lane & 15;
    const int chl = lane >> 4;
    float* ob = out + (size_t)roi * (CCH * PS * PS);

    for (int cp = 0; cp < 32; cp++) {
        const int c = 2 * warp + 16 * cp + chl;     // channel
        const __half* sp = &sout_h[c];
        float* op = &ob[c * 49];
#pragma unroll
        for (int s = 0; s < 4; s++) {
            int o = oA + 16 * s;
            if (s < 3 || o < 49) {
                if (s == 3 && oA != 0) continue;
                op[o] = __half2float(sp[o * SOUT_PAD]);
            }
        }
    }
}

extern "C" void kernel_launch(void* const* d_in, const int* in_sizes, int n_in,
                              void* d_out, int out_size)
{
    const float* bottom = (const float*)d_in[0];
    const float* rois   = (const float*)d_in[1];
    float* out = (float*)d_out;

    dim3 tgrid((HWSZ + 31) / 32, CCH / 32);
    transpose_kernel<<<tgrid, dim3(32, 8)>>>(bottom);
    crop_pool_kernel<<<NROIS, THREADS>>>(rois, out);
}

// round 9
// speedup vs baseline: 1.2853x; 1.0576x over previous
#include <cuda_runtime.h>
#include <cuda_fp16.h>

// Fixed problem shapes
#define NROIS 1024
#define CCH   512
#define HH    38
#define WW    50
#define HWSZ  (HH * WW)          // 1900
#define PRE   14                 // pooling_size * 2
#define PS    7

#define THREADS  128
#define NWARPS   (THREADS / 32)
#define NTASKS   49              // 49 windows (this CTA owns 256 channels)
#define CHB      256             // channels per CTA
#define SOUT_PAD 264             // halves per window row: 528B (16B-aligned), 2-way LDS max

// Transposed feature map in fp16: [cell = y*W + x][channel], 1.94 MB (L2-resident).
__device__ __align__(16) __half g_trh[HWSZ * CCH];

// ---------------- transpose+convert kernel: [C][H*W] fp32 -> [H*W][C] fp16 ----------------
__global__ __launch_bounds__(256)
void transpose_kernel(const float* __restrict__ bottom)
{
    __shared__ float t[32][33];
    const int c0 = blockIdx.x * 32;     // cell tile base
    const int h0 = blockIdx.y * 32;     // channel tile base
    const int tx = threadIdx.x;         // 0..31
    const int ty = threadIdx.y;         // 0..7

#pragma unroll
    for (int i = 0; i < 4; i++) {
        int ch = h0 + ty + i * 8;
        int cc = c0 + tx;
        t[ty + i * 8][tx] = (cc < HWSZ) ? bottom[ch * HWSZ + cc] : 0.0f;
    }
    __syncthreads();
#pragma unroll
    for (int i = 0; i < 4; i++) {
        int cc = c0 + ty + i * 8;
        int ch = h0 + tx;
        if (cc < HWSZ) g_trh[cc * CCH + ch] = __float2half(t[tx][ty + i * 8]);
    }
}

// ---------------- main kernel: one CTA per (ROI, channel-half) ----------------
__device__ __forceinline__ float grid_coord(float lo, float hi, float L, int j) {
    float t0 = (hi - lo) / L;
    float t2 = (lo + hi - L) / L;
    float base = -1.0f + (float)j * (2.0f / 13.0f);
    float g = t0 * base + t2;
    return (g + 1.0f) * 0.5f * L;
}

__device__ __forceinline__ __half2 u2h(unsigned u) { return *(__half2*)&u; }

__global__ __launch_bounds__(THREADS, 7)
void crop_pool_kernel(const float* __restrict__ rois,
                      float* __restrict__ out)
{
    __shared__ int   sxi[2][PRE];  __shared__ float sxw[2][PRE];
    __shared__ int   syi[2][PRE];  __shared__ float syw[2][PRE];
    __shared__ int4  soff[PRE * PRE];     // per-sample 4 corner offsets (half elements)
    __shared__ uint4 swth[PRE * PRE];     // per-sample 4 weights as broadcast half2
    __shared__ short s00tab[49];          // window -> first sample id
    __shared__ __align__(16) __half sout_h[49 * SOUT_PAD];   // staging (~25.3KB)

    const int roi    = blockIdx.x >> 1;
    const int chbase = (blockIdx.x & 1) * CHB;
    const int tid    = threadIdx.x;

    // ---- Phase 1: per-axis corner indices + weights (threads 0..27) ----
    if (tid < 2 * PRE) {
        const int isY = (tid >= PRE);
        const int j   = isY ? (tid - PRE) : tid;
        const float lo = rois[roi * 5 + (isY ? 2 : 1)] * (1.0f / 16.0f);
        const float hi = rois[roi * 5 + (isY ? 4 : 3)] * (1.0f / 16.0f);
        const float Lf = isY ? (float)(HH - 1) : (float)(WW - 1);
        const int   Li = isY ? (HH - 1) : (WW - 1);

        float ic = grid_coord(lo, hi, Lf, j);
        float f  = floorf(ic);
        float a  = ic - f;
        int i0 = (int)f;
        int i1 = i0 + 1;
        int i0c = min(max(i0, 0), Li);
        int i1c = min(max(i1, 0), Li);
        float w0 = (i0 >= 0 && i0 <= Li) ? (1.0f - a) : 0.0f;
        float w1 = (i1 >= 0 && i1 <= Li) ? a : 0.0f;

        if (!isY) {
            sxi[0][j] = i0c; sxi[1][j] = i1c; sxw[0][j] = w0; sxw[1][j] = w1;
        } else {
            syi[0][j] = i0c; syi[1][j] = i1c; syw[0][j] = w0; syw[1][j] = w1;
        }
    }
    // window -> s00 lookup (threads 32..80)
    if (tid >= 32 && tid < 32 + 49) {
        int win = tid - 32;
        int py = win / 7;
        int px = win - py * 7;
        s00tab[win] = (short)((2 * py) * PRE + 2 * px);
    }
    __syncthreads();

    // ---- Phase 2: per-sample packed corner offsets + half2 weights ----
#pragma unroll
    for (int sidb = 0; sidb < 2; sidb++) {
        int sid = tid + sidb * THREADS;
        if (sid < PRE * PRE) {
            const int jy = sid / PRE;
            const int jx = sid - jy * PRE;
            const int y0 = syi[0][jy], y1 = syi[1][jy];
            const int x0 = sxi[0][jx], x1 = sxi[1][jx];
            const float wy0 = syw[0][jy], wy1 = syw[1][jy];
            const float wx0 = sxw[0][jx], wx1 = sxw[1][jx];
            int4 o;
            o.x = (y0 * WW + x0) * CCH + chbase;
            o.y = (y0 * WW + x1) * CCH + chbase;
            o.z = (y1 * WW + x0) * CCH + chbase;
            o.w = (y1 * WW + x1) * CCH + chbase;
            uint4 w;
            __half2 h0 = __float2half2_rn(wy0 * wx0);
            __half2 h1 = __float2half2_rn(wy0 * wx1);
            __half2 h2 = __float2half2_rn(wy1 * wx0);
            __half2 h3 = __float2half2_rn(wy1 * wx1);
            w.x = *(unsigned*)&h0;
            w.y = *(unsigned*)&h1;
            w.z = *(unsigned*)&h2;
            w.w = *(unsigned*)&h3;
            soff[sid] = o;
            swth[sid] = w;
        }
    }
    __syncthreads();

    const int warp = tid >> 5;
    const int lane = tid & 31;
    const __half* __restrict__ trp = g_trh;

    // ---- Compute phase: 49 window-tasks, no intermediate barriers ----
    const int choff = lane * 8;     // 8 ch/lane covers this CTA's 256 channels
    for (int win = warp; win < NTASKS; win += NWARPS) {
        const int s00 = s00tab[win];

        __half2 m2[4];
#pragma unroll
        for (int s = 0; s < 4; s++) {
            const int sid = s00 + (s >> 1) * PRE + (s & 1);
            const int4  o  = soff[sid];
            const uint4 wh = swth[sid];
            const __half2 w0 = u2h(wh.x), w1 = u2h(wh.y);
            const __half2 w2 = u2h(wh.z), w3 = u2h(wh.w);
            uint4 c0 = __ldg((const uint4*)(trp + o.x + choff));
            uint4 c1 = __ldg((const uint4*)(trp + o.y + choff));
            uint4 c2 = __ldg((const uint4*)(trp + o.z + choff));
            uint4 c3 = __ldg((const uint4*)(trp + o.w + choff));
            const unsigned* u0  = (const unsigned*)&c0;
            const unsigned* u1  = (const unsigned*)&c1;
            const unsigned* u2p = (const unsigned*)&c2;
            const unsigned* u3  = (const unsigned*)&c3;
#pragma unroll
            for (int k = 0; k < 4; k++) {
                __half2 acc = __hmul2(w0, u2h(u0[k]));
                acc = __hfma2(w1, u2h(u1[k]), acc);
                acc = __hfma2(w2, u2h(u2p[k]), acc);
                acc = __hfma2(w3, u2h(u3[k]), acc);
                m2[k] = (s == 0) ? acc : __hmax2(m2[k], acc);
            }
        }
        // store raw half results: 16B per lane, banks 0..31 conflict-free
        *(uint4*)(&sout_h[win * SOUT_PAD + choff]) = *(uint4*)m2;
    }
    __syncthreads();

    // ---- Copy phase: half -> float, coalesced output, streaming stores ----
    // warp handles channel pair; lanes 0-15 -> c, 16-31 -> c+1; o = lane&15
    const int oA  = lane & 15;
    const int chl = lane >> 4;
    float* ob = out + (size_t)roi * (CCH * PS * PS) + (size_t)chbase * 49;

    for (int cp = 0; cp < 32; cp++) {
        const int c = 2 * warp + 8 * cp + chl;      // local channel (0..255)
        const __half* sp = &sout_h[c];
        float* op = &ob[c * 49];
#pragma unroll
        for (int s = 0; s < 4; s++) {
            int o = oA + 16 * s;
            if (s == 3) {
                if (oA == 0) __stcs(&op[48], __half2float(sp[48 * SOUT_PAD]));
            } else {
                __stcs(&op[o], __half2float(sp[o * SOUT_PAD]));
            }
        }
    }
}

extern "C" void kernel_launch(void* const* d_in, const int* in_sizes, int n_in,
                              void* d_out, int out_size)
{
    const float* bottom = (const float*)d_in[0];
    const float* rois   = (const float*)d_in[1];
    float* out = (float*)d_out;

    dim3 tgrid((HWSZ + 31) / 32, CCH / 32);
    transpose_kernel<<<tgrid, dim3(32, 8)>>>(bottom);
    crop_pool_kernel<<<NROIS * 2, THREADS>>>(rois, out);
}

// round 10
// speedup vs baseline: 1.3584x; 1.0569x over previous
#include <cuda_runtime.h>
#include <cuda_fp16.h>

// Fixed problem shapes
#define NROIS 1024
#define CCH   512
#define HH    38
#define WW    50
#define HWSZ  (HH * WW)          // 1900
#define PRE   14                 // pooling_size * 2
#define PS    7

#define THREADS  128
#define NWARPS   (THREADS / 32)
#define NTASKS   49              // 49 windows (this CTA owns 256 channels)
#define CHB      256             // channels per CTA
#define SOUT_PAD 264             // halves per window row: 528B (16B-aligned), 2-way LDS max

// Transposed feature map in fp16: [cell = y*W + x][channel], 1.94 MB (L2-resident).
__device__ __align__(16) __half g_trh[HWSZ * CCH];

// ---------------- transpose+convert kernel: [C][H*W] fp32 -> [H*W][C] fp16 ----------------
__global__ __launch_bounds__(256)
void transpose_kernel(const float* __restrict__ bottom)
{
    __shared__ float t[32][33];
    const int c0 = blockIdx.x * 32;     // cell tile base
    const int h0 = blockIdx.y * 32;     // channel tile base
    const int tx = threadIdx.x;         // 0..31
    const int ty = threadIdx.y;         // 0..7

#pragma unroll
    for (int i = 0; i < 4; i++) {
        int ch = h0 + ty + i * 8;
        int cc = c0 + tx;
        t[ty + i * 8][tx] = (cc < HWSZ) ? bottom[ch * HWSZ + cc] : 0.0f;
    }
    __syncthreads();
#pragma unroll
    for (int i = 0; i < 4; i++) {
        int cc = c0 + ty + i * 8;
        int ch = h0 + tx;
        if (cc < HWSZ) g_trh[cc * CCH + ch] = __float2half(t[tx][ty + i * 8]);
    }
}

// ---------------- main kernel: one CTA per (ROI, channel-half) ----------------
__device__ __forceinline__ float grid_coord(float lo, float hi, float L, int j) {
    float t0 = (hi - lo) / L;
    float t2 = (lo + hi - L) / L;
    float base = -1.0f + (float)j * (2.0f / 13.0f);
    float g = t0 * base + t2;
    return (g + 1.0f) * 0.5f * L;
}

__device__ __forceinline__ __half2 u2h(unsigned u) { return *(__half2*)&u; }

__global__ __launch_bounds__(THREADS, 7)
void crop_pool_kernel(const float* __restrict__ rois,
                      float* __restrict__ out)
{
    __shared__ int   sxi[2][PRE];  __shared__ float sxw[2][PRE];
    __shared__ int   syi[2][PRE];  __shared__ float syw[2][PRE];
    __shared__ uint2 soffs[PRE * PRE];    // per-sample 4 corner CELL indices, packed u16x4
    __shared__ uint4 swth[PRE * PRE];     // per-sample 4 weights as broadcast half2
    __shared__ short s00tab[49];          // window -> first sample id
    __shared__ __align__(16) __half sout_h[49 * SOUT_PAD];   // staging (~25.9KB)

    const int roi    = blockIdx.x >> 1;
    const int chbase = (blockIdx.x & 1) * CHB;
    const int tid    = threadIdx.x;

    // ---- Phase 1: per-axis corner indices + weights (threads 0..27) ----
    if (tid < 2 * PRE) {
        const int isY = (tid >= PRE);
        const int j   = isY ? (tid - PRE) : tid;
        const float lo = rois[roi * 5 + (isY ? 2 : 1)] * (1.0f / 16.0f);
        const float hi = rois[roi * 5 + (isY ? 4 : 3)] * (1.0f / 16.0f);
        const float Lf = isY ? (float)(HH - 1) : (float)(WW - 1);
        const int   Li = isY ? (HH - 1) : (WW - 1);

        float ic = grid_coord(lo, hi, Lf, j);
        float f  = floorf(ic);
        float a  = ic - f;
        int i0 = (int)f;
        int i1 = i0 + 1;
        int i0c = min(max(i0, 0), Li);
        int i1c = min(max(i1, 0), Li);
        float w0 = (i0 >= 0 && i0 <= Li) ? (1.0f - a) : 0.0f;
        float w1 = (i1 >= 0 && i1 <= Li) ? a : 0.0f;

        if (!isY) {
            sxi[0][j] = i0c; sxi[1][j] = i1c; sxw[0][j] = w0; sxw[1][j] = w1;
        } else {
            syi[0][j] = i0c; syi[1][j] = i1c; syw[0][j] = w0; syw[1][j] = w1;
        }
    }
    // window -> s00 lookup (threads 32..80)
    if (tid >= 32 && tid < 32 + 49) {
        int win = tid - 32;
        int py = win / 7;
        int px = win - py * 7;
        s00tab[win] = (short)((2 * py) * PRE + 2 * px);
    }
    __syncthreads();

    // ---- Phase 2: per-sample packed corner cells + half2 weights ----
#pragma unroll
    for (int sidb = 0; sidb < 2; sidb++) {
        int sid = tid + sidb * THREADS;
        if (sid < PRE * PRE) {
            const int jy = sid / PRE;
            const int jx = sid - jy * PRE;
            const int y0 = syi[0][jy], y1 = syi[1][jy];
            const int x0 = sxi[0][jx], x1 = sxi[1][jx];
            const float wy0 = syw[0][jy], wy1 = syw[1][jy];
            const float wx0 = sxw[0][jx], wx1 = sxw[1][jx];
            unsigned c00 = (unsigned)(y0 * WW + x0);
            unsigned c01 = (unsigned)(y0 * WW + x1);
            unsigned c10 = (unsigned)(y1 * WW + x0);
            unsigned c11 = (unsigned)(y1 * WW + x1);
            uint2 oc;
            oc.x = c00 | (c01 << 16);
            oc.y = c10 | (c11 << 16);
            uint4 w;
            __half2 h0 = __float2half2_rn(wy0 * wx0);
            __half2 h1 = __float2half2_rn(wy0 * wx1);
            __half2 h2 = __float2half2_rn(wy1 * wx0);
            __half2 h3 = __float2half2_rn(wy1 * wx1);
            w.x = *(unsigned*)&h0;
            w.y = *(unsigned*)&h1;
            w.z = *(unsigned*)&h2;
            w.w = *(unsigned*)&h3;
            soffs[sid] = oc;
            swth[sid]  = w;
        }
    }
    __syncthreads();

    const int warp = tid >> 5;
    const int lane = tid & 31;

    // ---- Compute phase: 49 window-tasks, no intermediate barriers ----
    const int choff  = lane * 8;                       // local half-offset (16B/lane)
    const __half* __restrict__ trpb = g_trh + chbase + choff;  // per-lane base

    for (int win = warp; win < NTASKS; win += NWARPS) {
        const int s00 = s00tab[win];

        __half2 m2[4];
#pragma unroll
        for (int s = 0; s < 4; s++) {
            const int sid = s00 + (s >> 1) * PRE + (s & 1);
            const uint2 oc = soffs[sid];
            const uint4 wh = swth[sid];
            const __half2 w0 = u2h(wh.x), w1 = u2h(wh.y);
            const __half2 w2 = u2h(wh.z), w3 = u2h(wh.w);
            const int a00 = (int)(oc.x & 0xFFFFu) << 9;
            const int a01 = (int)(oc.x >> 16)     << 9;
            const int a10 = (int)(oc.y & 0xFFFFu) << 9;
            const int a11 = (int)(oc.y >> 16)     << 9;
            uint4 c0 = __ldg((const uint4*)(trpb + a00));
            uint4 c1 = __ldg((const uint4*)(trpb + a01));
            uint4 c2 = __ldg((const uint4*)(trpb + a10));
            uint4 c3 = __ldg((const uint4*)(trpb + a11));
            const unsigned* u0  = (const unsigned*)&c0;
            const unsigned* u1  = (const unsigned*)&c1;
            const unsigned* u2p = (const unsigned*)&c2;
            const unsigned* u3  = (const unsigned*)&c3;
#pragma unroll
            for (int k = 0; k < 4; k++) {
                __half2 acc = __hmul2(w0, u2h(u0[k]));
                acc = __hfma2(w1, u2h(u1[k]), acc);
                acc = __hfma2(w2, u2h(u2p[k]), acc);
                acc = __hfma2(w3, u2h(u3[k]), acc);
                m2[k] = (s == 0) ? acc : __hmax2(m2[k], acc);
            }
        }
        // store raw half results: 16B per lane, banks 0..31 conflict-free
        *(uint4*)(&sout_h[win * SOUT_PAD + choff]) = *(uint4*)m2;
    }
    __syncthreads();

    // ---- Copy phase: half -> float, coalesced output, streaming stores ----
    // warp handles channel pair; lanes 0-15 -> c, 16-31 -> c+1; o = lane&15
    const int oA  = lane & 15;
    const int chl = lane >> 4;
    float* ob = out + (size_t)roi * (CCH * PS * PS) + (size_t)chbase * 49;

    for (int cp = 0; cp < 32; cp++) {
        const int c = 2 * warp + 8 * cp + chl;      // local channel (0..255)
        const __half* sp = &sout_h[c];
        float* op = &ob[c * 49];
#pragma unroll
        for (int s = 0; s < 4; s++) {
            int o = oA + 16 * s;
            if (s == 3) {
                if (oA == 0) __stcs(&op[48], __half2float(sp[48 * SOUT_PAD]));
            } else {
                __stcs(&op[o], __half2float(sp[o * SOUT_PAD]));
            }
        }
    }
}

extern "C" void kernel_launch(void* const* d_in, const int* in_sizes, int n_in,
                              void* d_out, int out_size)
{
    const float* bottom = (const float*)d_in[0];
    const float* rois   = (const float*)d_in[1];
    float* out = (float*)d_out;

    dim3 tgrid((HWSZ + 31) / 32, CCH / 32);
    transpose_kernel<<<tgrid, dim3(32, 8)>>>(bottom);
    crop_pool_kernel<<<NROIS * 2, THREADS>>>(rois, out);
}

// round 11
// speedup vs baseline: 1.3638x; 1.0040x over previous
#include <cuda_runtime.h>
#include <cuda_fp16.h>

// Fixed problem shapes
#define NROIS 1024
#define CCH   512
#define HH    38
#define WW    50
#define HWSZ  (HH * WW)          // 1900
#define PRE   14                 // pooling_size * 2
#define PS    7

#define THREADS  128
#define NWARPS   (THREADS / 32)
#define NTASKS   49              // 49 windows (this CTA owns 256 channels)
#define CHB      256             // channels per CTA
#define SOUT_PAD 264             // halves per window row: 528B (16B-aligned), 2-way LDS max

// Transposed feature map in fp16: [cell = y*W + x][channel], 1.94 MB (L2-resident).
__device__ __align__(16) __half g_trh[HWSZ * CCH];

// ---------------- transpose+convert kernel: [C][H*W] fp32 -> [H*W][C] fp16 ----------------
__global__ __launch_bounds__(256)
void transpose_kernel(const float* __restrict__ bottom)
{
    __shared__ float t[32][33];
    const int c0 = blockIdx.x * 32;     // cell tile base
    const int h0 = blockIdx.y * 32;     // channel tile base
    const int tx = threadIdx.x;         // 0..31
    const int ty = threadIdx.y;         // 0..7

#pragma unroll
    for (int i = 0; i < 4; i++) {
        int ch = h0 + ty + i * 8;
        int cc = c0 + tx;
        t[ty + i * 8][tx] = (cc < HWSZ) ? bottom[ch * HWSZ + cc] : 0.0f;
    }
    __syncthreads();
#pragma unroll
    for (int i = 0; i < 4; i++) {
        int cc = c0 + ty + i * 8;
        int ch = h0 + tx;
        if (cc < HWSZ) g_trh[cc * CCH + ch] = __float2half(t[tx][ty + i * 8]);
    }
}

// ---------------- main kernel: one CTA per (ROI, channel-half) ----------------
__device__ __forceinline__ float grid_coord(float lo, float hi, float L, int j) {
    float t0 = (hi - lo) / L;
    float t2 = (lo + hi - L) / L;
    float base = -1.0f + (float)j * (2.0f / 13.0f);
    float g = t0 * base + t2;
    return (g + 1.0f) * 0.5f * L;
}

__device__ __forceinline__ __half2 u2h(unsigned u) { return *(__half2*)&u; }

__global__ __launch_bounds__(THREADS, 7)
void crop_pool_kernel(const float* __restrict__ rois,
                      float* __restrict__ out)
{
    __shared__ int   sxi[2][PRE];  __shared__ float sxw[2][PRE];
    __shared__ int   syi[2][PRE];  __shared__ float syw[2][PRE];
    __shared__ uint2 soffs[PRE * PRE];    // per-sample 4 corner CELL indices, packed u16x4
    __shared__ uint4 swth[PRE * PRE];     // per-sample 4 weights as broadcast half2
    __shared__ short s00tab[49];          // window -> first sample id
    __shared__ __align__(16) __half sout_h[49 * SOUT_PAD];   // staging (~25.9KB)

    const int roi    = blockIdx.x >> 1;
    const int chbase = (blockIdx.x & 1) * CHB;
    const int tid    = threadIdx.x;

    // ---- Phase 1: per-axis corner indices + weights (threads 0..27) ----
    if (tid < 2 * PRE) {
        const int isY = (tid >= PRE);
        const int j   = isY ? (tid - PRE) : tid;
        const float lo = rois[roi * 5 + (isY ? 2 : 1)] * (1.0f / 16.0f);
        const float hi = rois[roi * 5 + (isY ? 4 : 3)] * (1.0f / 16.0f);
        const float Lf = isY ? (float)(HH - 1) : (float)(WW - 1);
        const int   Li = isY ? (HH - 1) : (WW - 1);

        float ic = grid_coord(lo, hi, Lf, j);
        float f  = floorf(ic);
        float a  = ic - f;
        int i0 = (int)f;
        int i1 = i0 + 1;
        int i0c = min(max(i0, 0), Li);
        int i1c = min(max(i1, 0), Li);
        float w0 = (i0 >= 0 && i0 <= Li) ? (1.0f - a) : 0.0f;
        float w1 = (i1 >= 0 && i1 <= Li) ? a : 0.0f;

        if (!isY) {
            sxi[0][j] = i0c; sxi[1][j] = i1c; sxw[0][j] = w0; sxw[1][j] = w1;
        } else {
            syi[0][j] = i0c; syi[1][j] = i1c; syw[0][j] = w0; syw[1][j] = w1;
        }
    }
    // window -> s00 lookup (threads 32..80)
    if (tid >= 32 && tid < 32 + 49) {
        int win = tid - 32;
        int py = win / 7;
        int px = win - py * 7;
        s00tab[win] = (short)((2 * py) * PRE + 2 * px);
    }
    __syncthreads();

    // ---- Phase 2: per-sample packed corner cells + half2 weights ----
#pragma unroll
    for (int sidb = 0; sidb < 2; sidb++) {
        int sid = tid + sidb * THREADS;
        if (sid < PRE * PRE) {
            const int jy = sid / PRE;
            const int jx = sid - jy * PRE;
            const int y0 = syi[0][jy], y1 = syi[1][jy];
            const int x0 = sxi[0][jx], x1 = sxi[1][jx];
            const float wy0 = syw[0][jy], wy1 = syw[1][jy];
            const float wx0 = sxw[0][jx], wx1 = sxw[1][jx];
            unsigned c00 = (unsigned)(y0 * WW + x0);
            unsigned c01 = (unsigned)(y0 * WW + x1);
            unsigned c10 = (unsigned)(y1 * WW + x0);
            unsigned c11 = (unsigned)(y1 * WW + x1);
            uint2 oc;
            oc.x = c00 | (c01 << 16);
            oc.y = c10 | (c11 << 16);
            uint4 w;
            __half2 h0 = __float2half2_rn(wy0 * wx0);
            __half2 h1 = __float2half2_rn(wy0 * wx1);
            __half2 h2 = __float2half2_rn(wy1 * wx0);
            __half2 h3 = __float2half2_rn(wy1 * wx1);
            w.x = *(unsigned*)&h0;
            w.y = *(unsigned*)&h1;
            w.z = *(unsigned*)&h2;
            w.w = *(unsigned*)&h3;
            soffs[sid] = oc;
            swth[sid]  = w;
        }
    }
    __syncthreads();

    const int warp = tid >> 5;
    const int lane = tid & 31;

    // ---- Compute phase: 49 window-tasks, no intermediate barriers ----
    const int choff  = lane * 8;                       // local half-offset (16B/lane)
    const __half* __restrict__ trpb = g_trh + chbase + choff;  // per-lane base

    for (int win = warp; win < NTASKS; win += NWARPS) {
        const int s00 = s00tab[win];

        __half2 m2[4];
#pragma unroll
        for (int s = 0; s < 4; s++) {
            const int sid = s00 + (s >> 1) * PRE + (s & 1);
            const uint2 oc = soffs[sid];
            const uint4 wh = swth[sid];
            const __half2 w0 = u2h(wh.x), w1 = u2h(wh.y);
            const __half2 w2 = u2h(wh.z), w3 = u2h(wh.w);
            const int a00 = (int)(oc.x & 0xFFFFu) << 9;
            const int a01 = (int)(oc.x >> 16)     << 9;
            const int a10 = (int)(oc.y & 0xFFFFu) << 9;
            const int a11 = (int)(oc.y >> 16)     << 9;
            uint4 c0 = __ldg((const uint4*)(trpb + a00));
            uint4 c1 = __ldg((const uint4*)(trpb + a01));
            uint4 c2 = __ldg((const uint4*)(trpb + a10));
            uint4 c3 = __ldg((const uint4*)(trpb + a11));
            const unsigned* u0  = (const unsigned*)&c0;
            const unsigned* u1  = (const unsigned*)&c1;
            const unsigned* u2p = (const unsigned*)&c2;
            const unsigned* u3  = (const unsigned*)&c3;
#pragma unroll
            for (int k = 0; k < 4; k++) {
                __half2 acc = __hmul2(w0, u2h(u0[k]));
                acc = __hfma2(w1, u2h(u1[k]), acc);
                acc = __hfma2(w2, u2h(u2p[k]), acc);
                acc = __hfma2(w3, u2h(u3[k]), acc);
                m2[k] = (s == 0) ? acc : __hmax2(m2[k], acc);
            }
        }
        // store raw half results: 16B per lane, banks 0..31 conflict-free
        *(uint4*)(&sout_h[win * SOUT_PAD + choff]) = *(uint4*)m2;
    }
    __syncthreads();

    // ---- Copy phase: shuffle-widened, 128B-contiguous store runs ----
    // Warp step = 4 channels. lanes 0-15: pair (c0,c0+1); lanes 16-31: pair (c0+2,c0+3).
    const int oL    = lane & 15;
    const int halfp = lane >> 4;
    float* ob = out + (size_t)roi * (CCH * PS * PS) + (size_t)chbase * 49;

    for (int it = warp; it < CHB / 4; it += NWARPS) {
        const int c0 = it * 4;
        const __half* colbase = &sout_h[c0 + 2 * halfp];

        // main: o = 0..31 via two strided half2 reads + 2 shuffles
        unsigned a = *(const unsigned*)&colbase[(oL)      * SOUT_PAD];
        unsigned b = *(const unsigned*)&colbase[(oL + 16) * SOUT_PAD];
        unsigned ax = __shfl_xor_sync(0xffffffffu, a, 16);
        unsigned bx = __shfl_xor_sync(0xffffffffu, b, 16);
        // p0: pair (c0,c0+1) at o = lane ; p1: pair (c0+2,c0+3) at o = lane
        unsigned p0 = (lane < 16) ? a  : bx;
        unsigned p1 = (lane < 16) ? ax : b;
        float2 f0 = __half22float2(u2h(p0));
        float2 f1 = __half22float2(u2h(p1));
        __stcs(&ob[(c0 + 0) * 49 + lane], f0.x);   // 128B contiguous run
        __stcs(&ob[(c0 + 1) * 49 + lane], f0.y);
        __stcs(&ob[(c0 + 2) * 49 + lane], f1.x);
        __stcs(&ob[(c0 + 3) * 49 + lane], f1.y);

        // tail: o = 32..47 (all 32 lanes, own pair), plus o=48 by oL==0
        {
            const int o = 32 + oL;
            const int cA = c0 + 2 * halfp;
            unsigned t = *(const unsigned*)&colbase[o * SOUT_PAD];
            float2 ft = __half22float2(u2h(t));
            __stcs(&ob[cA * 49 + o],       ft.x);
            __stcs(&ob[(cA + 1) * 49 + o], ft.y);
            if (oL == 0) {
                unsigned t2 = *(const unsigned*)&colbase[48 * SOUT_PAD];
                float2 f2 = __half22float2(u2h(t2));
                __stcs(&ob[cA * 49 + 48],       f2.x);
                __stcs(&ob[(cA + 1) * 49 + 48], f2.y);
            }
        }
    }
}

extern "C" void kernel_launch(void* const* d_in, const int* in_sizes, int n_in,
                              void* d_out, int out_size)
{
    const float* bottom = (const float*)d_in[0];
    const float* rois   = (const float*)d_in[1];
    float* out = (float*)d_out;

    dim3 tgrid((HWSZ + 31) / 32, CCH / 32);
    transpose_kernel<<<tgrid, dim3(32, 8)>>>(bottom);
    crop_pool_kernel<<<NROIS * 2, THREADS>>>(rois, out);
}

// round 12
// speedup vs baseline: 1.3788x; 1.0110x over previous
#include <cuda_runtime.h>
#include <cuda_fp16.h>

// Fixed problem shapes
#define NROIS 1024
#define CCH   512
#define HH    38
#define WW    50
#define HWSZ  (HH * WW)          // 1900
#define PRE   14                 // pooling_size * 2
#define PS    7

#define THREADS  128
#define NWARPS   (THREADS / 32)
#define NTASKS   49              // 49 windows (this CTA owns 256 channels)
#define CHB      256             // channels per CTA
#define SOUT_PAD 264             // halves per window row: 528B (16B-aligned), 2-way LDS max

// Transposed feature map in fp16: [cell = y*W + x][channel], 1.94 MB (L2-resident).
__device__ __align__(16) __half g_trh[HWSZ * CCH];

// ---------------- transpose+convert kernel: [C][H*W] fp32 -> [H*W][C] fp16 ----------------
// 64-channel x 32-cell tiles: 128B coalesced loads AND 128B half2 stores.
__global__ __launch_bounds__(256)
void transpose_kernel(const float* __restrict__ bottom)
{
    __shared__ float t[64][33];
    const int c0 = blockIdx.x * 32;     // cell tile base
    const int h0 = blockIdx.y * 64;     // channel tile base
    const int tx = threadIdx.x;         // 0..31
    const int ty = threadIdx.y;         // 0..7

#pragma unroll
    for (int i = 0; i < 8; i++) {
        int ch = h0 + ty + i * 8;
        int cc = c0 + tx;
        t[ty + i * 8][tx] = (cc < HWSZ) ? bottom[ch * HWSZ + cc] : 0.0f;
    }
    __syncthreads();
#pragma unroll
    for (int i = 0; i < 4; i++) {
        int cc = c0 + ty + i * 8;
        if (cc < HWSZ) {
            __half2 v = __floats2half2_rn(t[2 * tx][ty + i * 8], t[2 * tx + 1][ty + i * 8]);
            *(__half2*)&g_trh[cc * CCH + h0 + 2 * tx] = v;
        }
    }
    // PDL: signal dependents after this CTA's stores are issued
    asm volatile("griddepcontrol.launch_dependents;" ::: "memory");
}

// ---------------- main kernel: one CTA per (ROI, channel-half) ----------------
__device__ __forceinline__ float grid_coord(float lo, float hi, float L, int j) {
    float t0 = (hi - lo) / L;
    float t2 = (lo + hi - L) / L;
    float base = -1.0f + (float)j * (2.0f / 13.0f);
    float g = t0 * base + t2;
    return (g + 1.0f) * 0.5f * L;
}

__device__ __forceinline__ __half2 u2h(unsigned u) { return *(__half2*)&u; }

__global__ __launch_bounds__(THREADS, 7)
void crop_pool_kernel(const float* __restrict__ rois,
                      float* __restrict__ out)
{
    __shared__ int   sxi[2][PRE];  __shared__ float sxw[2][PRE];
    __shared__ int   syi[2][PRE];  __shared__ float syw[2][PRE];
    __shared__ uint2 soffs[PRE * PRE];    // per-sample 4 corner CELL indices, packed u16x4
    __shared__ uint4 swth[PRE * PRE];     // per-sample 4 weights as broadcast half2
    __shared__ short s00tab[49];          // window -> first sample id
    __shared__ __align__(16) __half sout_h[49 * SOUT_PAD];   // staging (~25.9KB)

    const int roi    = blockIdx.x >> 1;
    const int chbase = (blockIdx.x & 1) * CHB;
    const int tid    = threadIdx.x;

    // ---- Phase 1: per-axis corner indices + weights (threads 0..27) ----
    if (tid < 2 * PRE) {
        const int isY = (tid >= PRE);
        const int j   = isY ? (tid - PRE) : tid;
        const float lo = rois[roi * 5 + (isY ? 2 : 1)] * (1.0f / 16.0f);
        const float hi = rois[roi * 5 + (isY ? 4 : 3)] * (1.0f / 16.0f);
        const float Lf = isY ? (float)(HH - 1) : (float)(WW - 1);
        const int   Li = isY ? (HH - 1) : (WW - 1);

        float ic = grid_coord(lo, hi, Lf, j);
        float f  = floorf(ic);
        float a  = ic - f;
        int i0 = (int)f;
        int i1 = i0 + 1;
        int i0c = min(max(i0, 0), Li);
        int i1c = min(max(i1, 0), Li);
        float w0 = (i0 >= 0 && i0 <= Li) ? (1.0f - a) : 0.0f;
        float w1 = (i1 >= 0 && i1 <= Li) ? a : 0.0f;

        if (!isY) {
            sxi[0][j] = i0c; sxi[1][j] = i1c; sxw[0][j] = w0; sxw[1][j] = w1;
        } else {
            syi[0][j] = i0c; syi[1][j] = i1c; syw[0][j] = w0; syw[1][j] = w1;
        }
    }
    // window -> s00 lookup (threads 32..80)
    if (tid >= 32 && tid < 32 + 49) {
        int win = tid - 32;
        int py = win / 7;
        int px = win - py * 7;
        s00tab[win] = (short)((2 * py) * PRE + 2 * px);
    }
    __syncthreads();

    // ---- Phase 2: per-sample packed corner cells + half2 weights ----
#pragma unroll
    for (int sidb = 0; sidb < 2; sidb++) {
        int sid = tid + sidb * THREADS;
        if (sid < PRE * PRE) {
            const int jy = sid / PRE;
            const int jx = sid - jy * PRE;
            const int y0 = syi[0][jy], y1 = syi[1][jy];
            const int x0 = sxi[0][jx], x1 = sxi[1][jx];
            const float wy0 = syw[0][jy], wy1 = syw[1][jy];
            const float wx0 = sxw[0][jx], wx1 = sxw[1][jx];
            unsigned c00 = (unsigned)(y0 * WW + x0);
            unsigned c01 = (unsigned)(y0 * WW + x1);
            unsigned c10 = (unsigned)(y1 * WW + x0);
            unsigned c11 = (unsigned)(y1 * WW + x1);
            uint2 oc;
            oc.x = c00 | (c01 << 16);
            oc.y = c10 | (c11 << 16);
            uint4 w;
            __half2 h0 = __float2half2_rn(wy0 * wx0);
            __half2 h1 = __float2half2_rn(wy0 * wx1);
            __half2 h2 = __float2half2_rn(wy1 * wx0);
            __half2 h3 = __float2half2_rn(wy1 * wx1);
            w.x = *(unsigned*)&h0;
            w.y = *(unsigned*)&h1;
            w.z = *(unsigned*)&h2;
            w.w = *(unsigned*)&h3;
            soffs[sid] = oc;
            swth[sid]  = w;
        }
    }
    __syncthreads();

    // PDL: wait for transpose grid's stores to be visible before reading g_trh
    asm volatile("griddepcontrol.wait;" ::: "memory");

    const int warp = tid >> 5;
    const int lane = tid & 31;

    // ---- Compute phase: 49 window-tasks, no intermediate barriers ----
    const int choff  = lane * 8;                       // local half-offset (16B/lane)
    const __half* __restrict__ trpb = g_trh + chbase + choff;  // per-lane base

    for (int win = warp; win < NTASKS; win += NWARPS) {
        const int s00 = s00tab[win];

        __half2 m2[4];
#pragma unroll
        for (int s = 0; s < 4; s++) {
            const int sid = s00 + (s >> 1) * PRE + (s & 1);
            const uint2 oc = soffs[sid];
            const uint4 wh = swth[sid];
            const __half2 w0 = u2h(wh.x), w1 = u2h(wh.y);
            const __half2 w2 = u2h(wh.z), w3 = u2h(wh.w);
            const int a00 = (int)(oc.x & 0xFFFFu) << 9;
            const int a01 = (int)(oc.x >> 16)     << 9;
            const int a10 = (int)(oc.y & 0xFFFFu) << 9;
            const int a11 = (int)(oc.y >> 16)     << 9;
            uint4 c0 = __ldg((const uint4*)(trpb + a00));
            uint4 c1 = __ldg((const uint4*)(trpb + a01));
            uint4 c2 = __ldg((const uint4*)(trpb + a10));
            uint4 c3 = __ldg((const uint4*)(trpb + a11));
            const unsigned* u0  = (const unsigned*)&c0;
            const unsigned* u1  = (const unsigned*)&c1;
            const unsigned* u2p = (const unsigned*)&c2;
            const unsigned* u3  = (const unsigned*)&c3;
#pragma unroll
            for (int k = 0; k < 4; k++) {
                __half2 acc = __hmul2(w0, u2h(u0[k]));
                acc = __hfma2(w1, u2h(u1[k]), acc);
                acc = __hfma2(w2, u2h(u2p[k]), acc);
                acc = __hfma2(w3, u2h(u3[k]), acc);
                m2[k] = (s == 0) ? acc : __hmax2(m2[k], acc);
            }
        }
        // store raw half results: 16B per lane, banks 0..31 conflict-free
        *(uint4*)(&sout_h[win * SOUT_PAD + choff]) = *(uint4*)m2;
    }
    __syncthreads();

    // ---- Copy phase: shuffle-widened, 128B-contiguous store runs ----
    // Warp step = 4 channels. lanes 0-15: pair (c0,c0+1); lanes 16-31: pair (c0+2,c0+3).
    const int oL    = lane & 15;
    const int halfp = lane >> 4;
    float* ob = out + (size_t)roi * (CCH * PS * PS) + (size_t)chbase * 49;

    for (int it = warp; it < CHB / 4; it += NWARPS) {
        const int c0 = it * 4;
        const __half* colbase = &sout_h[c0 + 2 * halfp];

        // main: o = 0..31 via two strided half2 reads + 2 shuffles
        unsigned a = *(const unsigned*)&colbase[(oL)      * SOUT_PAD];
        unsigned b = *(const unsigned*)&colbase[(oL + 16) * SOUT_PAD];
        unsigned ax = __shfl_xor_sync(0xffffffffu, a, 16);
        unsigned bx = __shfl_xor_sync(0xffffffffu, b, 16);
        // p0: pair (c0,c0+1) at o = lane ; p1: pair (c0+2,c0+3) at o = lane
        unsigned p0 = (lane < 16) ? a  : bx;
        unsigned p1 = (lane < 16) ? ax : b;
        float2 f0 = __half22float2(u2h(p0));
        float2 f1 = __half22float2(u2h(p1));
        __stcs(&ob[(c0 + 0) * 49 + lane], f0.x);   // 128B contiguous run
        __stcs(&ob[(c0 + 1) * 49 + lane], f0.y);
        __stcs(&ob[(c0 + 2) * 49 + lane], f1.x);
        __stcs(&ob[(c0 + 3) * 49 + lane], f1.y);

        // tail: o = 32..47 (all 32 lanes, own pair), plus o=48 by oL==0
        {
            const int o = 32 + oL;
            const int cA = c0 + 2 * halfp;
            unsigned t = *(const unsigned*)&colbase[o * SOUT_PAD];
            float2 ft = __half22float2(u2h(t));
            __stcs(&ob[cA * 49 + o],       ft.x);
            __stcs(&ob[(cA + 1) * 49 + o], ft.y);
            if (oL == 0) {
                unsigned t2 = *(const unsigned*)&colbase[48 * SOUT_PAD];
                float2 f2 = __half22float2(u2h(t2));
                __stcs(&ob[cA * 49 + 48],       f2.x);
                __stcs(&ob[(cA + 1) * 49 + 48], f2.y);
            }
        }
    }
}

extern "C" void kernel_launch(void* const* d_in, const int* in_sizes, int n_in,
                              void* d_out, int out_size)
{
    const float* bottom = (const float*)d_in[0];
    const float* rois   = (const float*)d_in[1];
    float* out = (float*)d_out;

    // transpose: 64-ch x 32-cell tiles
    dim3 tgrid((HWSZ + 31) / 32, CCH / 64);
    transpose_kernel<<<tgrid, dim3(32, 8)>>>(bottom);

    // crop kernel with Programmatic Dependent Launch: overlaps its setup
    // phases with the transpose tail; griddepcontrol.wait guards g_trh reads.
    cudaLaunchConfig_t cfg = {};
    cfg.gridDim  = dim3(NROIS * 2, 1, 1);
    cfg.blockDim = dim3(THREADS, 1, 1);
    cfg.dynamicSmemBytes = 0;
    cfg.stream = 0;
    cudaLaunchAttribute attrs[1];
    attrs[0].id = cudaLaunchAttributeProgrammaticStreamSerialization;
    attrs[0].val.programmaticStreamSerializationAllowed = 1;
    cfg.attrs = attrs;
    cfg.numAttrs = 1;
    cudaLaunchKernelEx(&cfg, crop_pool_kernel, rois, out);
}

// round 13
// speedup vs baseline: 1.3803x; 1.0012x over previous
#include <cuda_runtime.h>
#include <cuda_fp16.h>

// Fixed problem shapes
#define NROIS 1024
#define CCH   512
#define HH    38
#define WW    50
#define HWSZ  (HH * WW)          // 1900
#define PRE   14                 // pooling_size * 2
#define PS    7

#define THREADS  128
#define NWARPS   (THREADS / 32)
#define CHB      256             // channels per CTA
#define SOUT_PAD 264             // halves per window row: 528B (16B-aligned), 2-way LDS max
#define SOUT_ROWS 52             // 48 pooled windows + 4 sample-rows for window 48

// Transposed feature map in fp16: [cell = y*W + x][channel], 1.94 MB (L2-resident).
__device__ __align__(16) __half g_trh[HWSZ * CCH];

// ---------------- transpose+convert kernel: [C][H*W] fp32 -> [H*W][C] fp16 ----------------
__global__ __launch_bounds__(256)
void transpose_kernel(const float* __restrict__ bottom)
{
    __shared__ float t[64][33];
    const int c0 = blockIdx.x * 32;     // cell tile base
    const int h0 = blockIdx.y * 64;     // channel tile base
    const int tx = threadIdx.x;         // 0..31
    const int ty = threadIdx.y;         // 0..7

#pragma unroll
    for (int i = 0; i < 8; i++) {
        int ch = h0 + ty + i * 8;
        int cc = c0 + tx;
        t[ty + i * 8][tx] = (cc < HWSZ) ? bottom[ch * HWSZ + cc] : 0.0f;
    }
    __syncthreads();
#pragma unroll
    for (int i = 0; i < 4; i++) {
        int cc = c0 + ty + i * 8;
        if (cc < HWSZ) {
            __half2 v = __floats2half2_rn(t[2 * tx][ty + i * 8], t[2 * tx + 1][ty + i * 8]);
            *(__half2*)&g_trh[cc * CCH + h0 + 2 * tx] = v;
        }
    }
    asm volatile("griddepcontrol.launch_dependents;" ::: "memory");
}

// ---------------- main kernel: one CTA per (ROI, channel-half) ----------------
__device__ __forceinline__ float grid_coord(float lo, float hi, float L, int j) {
    float t0 = (hi - lo) / L;
    float t2 = (lo + hi - L) / L;
    float base = -1.0f + (float)j * (2.0f / 13.0f);
    float g = t0 * base + t2;
    return (g + 1.0f) * 0.5f * L;
}

__device__ __forceinline__ __half2 u2h(unsigned u) { return *(__half2*)&u; }

// One bilinear sample for 8 channels (lane-local), given a fused record.
__device__ __forceinline__ void sample8(const __half* __restrict__ trpb,
                                        uint4 rec, __half2 acc[4], bool first)
{
    const __half2 p01 = u2h(rec.z);       // (w00, w01)
    const __half2 p23 = u2h(rec.w);       // (w10, w11)
    const __half2 w0 = __low2half2(p01), w1 = __high2half2(p01);
    const __half2 w2 = __low2half2(p23), w3 = __high2half2(p23);
    const int a00 = (int)(rec.x & 0xFFFFu) << 9;
    const int a01 = (int)(rec.x >> 16)     << 9;
    const int a10 = (int)(rec.y & 0xFFFFu) << 9;
    const int a11 = (int)(rec.y >> 16)     << 9;
    uint4 c0 = __ldg((const uint4*)(trpb + a00));
    uint4 c1 = __ldg((const uint4*)(trpb + a01));
    uint4 c2 = __ldg((const uint4*)(trpb + a10));
    uint4 c3 = __ldg((const uint4*)(trpb + a11));
    const unsigned* u0 = (const unsigned*)&c0;
    const unsigned* u1 = (const unsigned*)&c1;
    const unsigned* u2p = (const unsigned*)&c2;
    const unsigned* u3 = (const unsigned*)&c3;
#pragma unroll
    for (int k = 0; k < 4; k++) {
        __half2 v = __hmul2(w0, u2h(u0[k]));
        v = __hfma2(w1, u2h(u1[k]), v);
        v = __hfma2(w2, u2h(u2p[k]), v);
        v = __hfma2(w3, u2h(u3[k]), v);
        acc[k] = first ? v : __hmax2(acc[k], v);
    }
}

__global__ __launch_bounds__(THREADS, 7)
void crop_pool_kernel(const float* __restrict__ rois,
                      float* __restrict__ out)
{
    __shared__ int   sxi[2][PRE];  __shared__ float sxw[2][PRE];
    __shared__ int   syi[2][PRE];  __shared__ float syw[2][PRE];
    __shared__ uint4 srec[PRE * PRE];     // fused: cells u16x4 + 4 weights (half)
    __shared__ short s00tab[49];          // window -> first sample id
    __shared__ __align__(16) __half sout_h[SOUT_ROWS * SOUT_PAD];   // ~26.8KB

    const int roi    = blockIdx.x >> 1;
    const int chbase = (blockIdx.x & 1) * CHB;
    const int tid    = threadIdx.x;

    // ---- Phase 1: per-axis corner indices + weights (threads 0..27) ----
    if (tid < 2 * PRE) {
        const int isY = (tid >= PRE);
        const int j   = isY ? (tid - PRE) : tid;
        const float lo = rois[roi * 5 + (isY ? 2 : 1)] * (1.0f / 16.0f);
        const float hi = rois[roi * 5 + (isY ? 4 : 3)] * (1.0f / 16.0f);
        const float Lf = isY ? (float)(HH - 1) : (float)(WW - 1);
        const int   Li = isY ? (HH - 1) : (WW - 1);

        float ic = grid_coord(lo, hi, Lf, j);
        float f  = floorf(ic);
        float a  = ic - f;
        int i0 = (int)f;
        int i1 = i0 + 1;
        int i0c = min(max(i0, 0), Li);
        int i1c = min(max(i1, 0), Li);
        float w0 = (i0 >= 0 && i0 <= Li) ? (1.0f - a) : 0.0f;
        float w1 = (i1 >= 0 && i1 <= Li) ? a : 0.0f;

        if (!isY) {
            sxi[0][j] = i0c; sxi[1][j] = i1c; sxw[0][j] = w0; sxw[1][j] = w1;
        } else {
            syi[0][j] = i0c; syi[1][j] = i1c; syw[0][j] = w0; syw[1][j] = w1;
        }
    }
    // window -> s00 lookup (threads 32..80)
    if (tid >= 32 && tid < 32 + 49) {
        int win = tid - 32;
        int py = win / 7;
        int px = win - py * 7;
        s00tab[win] = (short)((2 * py) * PRE + 2 * px);
    }
    __syncthreads();

    // ---- Phase 2: fused per-sample records ----
#pragma unroll
    for (int sidb = 0; sidb < 2; sidb++) {
        int sid = tid + sidb * THREADS;
        if (sid < PRE * PRE) {
            const int jy = sid / PRE;
            const int jx = sid - jy * PRE;
            const int y0 = syi[0][jy], y1 = syi[1][jy];
            const int x0 = sxi[0][jx], x1 = sxi[1][jx];
            const float wy0 = syw[0][jy], wy1 = syw[1][jy];
            const float wx0 = sxw[0][jx], wx1 = sxw[1][jx];
            uint4 r;
            r.x = (unsigned)(y0 * WW + x0) | ((unsigned)(y0 * WW + x1) << 16);
            r.y = (unsigned)(y1 * WW + x0) | ((unsigned)(y1 * WW + x1) << 16);
            // 4 products rounded once from fp32 (same precision as before)
            __half2 p01 = __floats2half2_rn(wy0 * wx0, wy0 * wx1);
            __half2 p23 = __floats2half2_rn(wy1 * wx0, wy1 * wx1);
            r.z = *(unsigned*)&p01;
            r.w = *(unsigned*)&p23;
            srec[sid] = r;
        }
    }
    __syncthreads();

    // PDL: wait for transpose grid's stores before reading g_trh
    asm volatile("griddepcontrol.wait;" ::: "memory");

    const int warp = tid >> 5;
    const int lane = tid & 31;

    // ---- Compute phase: 12 windows per warp + 1 shared sample of window 48 ----
    const int choff  = lane * 8;                       // local half-offset (16B/lane)
    const __half* __restrict__ trpb = g_trh + chbase + choff;

    for (int win = warp; win < 48; win += NWARPS) {
        const int s00 = s00tab[win];
        __half2 m2[4];
#pragma unroll
        for (int s = 0; s < 4; s++) {
            const int sid = s00 + (s >> 1) * PRE + (s & 1);
            sample8(trpb, srec[sid], m2, s == 0);
        }
        *(uint4*)(&sout_h[win * SOUT_PAD + choff]) = *(uint4*)m2;
    }
    // window 48: each warp computes ONE sample, staged to rows 48..51
    {
        const int s00 = s00tab[48];
        const int sid = s00 + (warp >> 1) * PRE + (warp & 1);
        __half2 m2[4];
        sample8(trpb, srec[sid], m2, true);
        *(uint4*)(&sout_h[(48 + warp) * SOUT_PAD + choff]) = *(uint4*)m2;
    }
    __syncthreads();

    // ---- Copy phase: shuffle-widened, 128B-contiguous store runs ----
    const int oL    = lane & 15;
    const int halfp = lane >> 4;
    float* ob = out + (size_t)roi * (CCH * PS * PS) + (size_t)chbase * 49;

    for (int it = warp; it < CHB / 4; it += NWARPS) {
        const int c0 = it * 4;
        const __half* colbase = &sout_h[c0 + 2 * halfp];

        // main: o = 0..31 via two strided half2 reads + 2 shuffles
        unsigned a = *(const unsigned*)&colbase[(oL)      * SOUT_PAD];
        unsigned b = *(const unsigned*)&colbase[(oL + 16) * SOUT_PAD];
        unsigned ax = __shfl_xor_sync(0xffffffffu, a, 16);
        unsigned bx = __shfl_xor_sync(0xffffffffu, b, 16);
        unsigned p0 = (lane < 16) ? a  : bx;
        unsigned p1 = (lane < 16) ? ax : b;
        float2 f0 = __half22float2(u2h(p0));
        float2 f1 = __half22float2(u2h(p1));
        __stcs(&ob[(c0 + 0) * 49 + lane], f0.x);   // 128B contiguous run
        __stcs(&ob[(c0 + 1) * 49 + lane], f0.y);
        __stcs(&ob[(c0 + 2) * 49 + lane], f1.x);
        __stcs(&ob[(c0 + 3) * 49 + lane], f1.y);

        // tail: o = 32..47 (all lanes, own pair); o = 48 = hmax of rows 48..51
        {
            const int o = 32 + oL;
            const int cA = c0 + 2 * halfp;
            unsigned t = *(const unsigned*)&colbase[o * SOUT_PAD];
            float2 ft = __half22float2(u2h(t));
            __stcs(&ob[cA * 49 + o],       ft.x);
            __stcs(&ob[(cA + 1) * 49 + o], ft.y);
            if (oL == 0) {
                unsigned t0 = *(const unsigned*)&colbase[48 * SOUT_PAD];
                unsigned t1 = *(const unsigned*)&colbase[49 * SOUT_PAD];
                unsigned t2 = *(const unsigned*)&colbase[50 * SOUT_PAD];
                unsigned t3 = *(const unsigned*)&colbase[51 * SOUT_PAD];
                __half2 mm = __hmax2(__hmax2(u2h(t0), u2h(t1)),
                                     __hmax2(u2h(t2), u2h(t3)));
                float2 f2 = __half22float2(mm);
                __stcs(&ob[cA * 49 + 48],       f2.x);
                __stcs(&ob[(cA + 1) * 49 + 48], f2.y);
            }
        }
    }
}

extern "C" void kernel_launch(void* const* d_in, const int* in_sizes, int n_in,
                              void* d_out, int out_size)
{
    const float* bottom = (const float*)d_in[0];
    const float* rois   = (const float*)d_in[1];
    float* out = (float*)d_out;

    // transpose: 64-ch x 32-cell tiles
    dim3 tgrid((HWSZ + 31) / 32, CCH / 64);
    transpose_kernel<<<tgrid, dim3(32, 8)>>>(bottom);

    // crop kernel with PDL: setup overlaps the transpose tail.
    cudaLaunchConfig_t cfg = {};
    cfg.gridDim  = dim3(NROIS * 2, 1, 1);
    cfg.blockDim = dim3(THREADS, 1, 1);
    cfg.dynamicSmemBytes = 0;
    cfg.stream = 0;
    cudaLaunchAttribute attrs[1];
    attrs[0].id = cudaLaunchAttributeProgrammaticStreamSerialization;
    attrs[0].val.programmaticStreamSerializationAllowed = 1;
    cfg.attrs = attrs;
    cfg.numAttrs = 1;
    cudaLaunchKernelEx(&cfg, crop_pool_kernel, rois, out);
}

// round 15
// speedup vs baseline: 1.4147x; 1.0249x over previous
#include <cuda_runtime.h>
#include <cuda_fp16.h>

// Fixed problem shapes
#define NROIS 1024
#define CCH   512
#define HH    38
#define WW    50
#define HWSZ  (HH * WW)          // 1900
#define PRE   14                 // pooling_size * 2
#define PS    7

#define THREADS  128
#define NWARPS   (THREADS / 32)
#define NTASKS   49              // 49 windows (this CTA owns 256 channels)
#define CHB      256             // channels per CTA
#define SOUT_PAD 264             // halves per window row: 528B (16B-aligned), 2-way LDS max

// Transposed feature map in fp16: [cell = y*W + x][channel], 1.94 MB (L2-resident).
__device__ __align__(16) __half g_trh[HWSZ * CCH];

// ---------------- transpose+convert kernel: [C][H*W] fp32 -> [H*W][C] fp16 ----------------
__global__ __launch_bounds__(256)
void transpose_kernel(const float* __restrict__ bottom)
{
    __shared__ float t[64][33];
    const int c0 = blockIdx.x * 32;     // cell tile base
    const int h0 = blockIdx.y * 64;     // channel tile base
    const int tx = threadIdx.x;         // 0..31
    const int ty = threadIdx.y;         // 0..7

#pragma unroll
    for (int i = 0; i < 8; i++) {
        int ch = h0 + ty + i * 8;
        int cc = c0 + tx;
        t[ty + i * 8][tx] = (cc < HWSZ) ? bottom[ch * HWSZ + cc] : 0.0f;
    }
    __syncthreads();
#pragma unroll
    for (int i = 0; i < 4; i++) {
        int cc = c0 + ty + i * 8;
        if (cc < HWSZ) {
            __half2 v = __floats2half2_rn(t[2 * tx][ty + i * 8], t[2 * tx + 1][ty + i * 8]);
            *(__half2*)&g_trh[cc * CCH + h0 + 2 * tx] = v;
        }
    }
    asm volatile("griddepcontrol.launch_dependents;" ::: "memory");
}

// ---------------- main kernel: one CTA per (ROI, channel-half) ----------------
__device__ __forceinline__ float grid_coord(float lo, float hi, float L, int j) {
    float t0 = (hi - lo) / L;
    float t2 = (lo + hi - L) / L;
    float base = -1.0f + (float)j * (2.0f / 13.0f);
    float g = t0 * base + t2;
    return (g + 1.0f) * 0.5f * L;
}

__device__ __forceinline__ __half2 u2h(unsigned u) { return *(__half2*)&u; }

// One bilinear sample for 8 channels (lane-local), given a fused record.
__device__ __forceinline__ void sample8(const __half* __restrict__ trpb,
                                        uint4 rec, __half2 acc[4], bool first)
{
    const __half2 p01 = u2h(rec.z);       // (w00, w01)
    const __half2 p23 = u2h(rec.w);       // (w10, w11)
    const __half2 w0 = __low2half2(p01), w1 = __high2half2(p01);
    const __half2 w2 = __low2half2(p23), w3 = __high2half2(p23);
    const int a00 = (int)(rec.x & 0xFFFFu) << 9;
    const int a01 = (int)(rec.x >> 16)     << 9;
    const int a10 = (int)(rec.y & 0xFFFFu) << 9;
    const int a11 = (int)(rec.y >> 16)     << 9;
    uint4 c0 = __ldg((const uint4*)(trpb + a00));
    uint4 c1 = __ldg((const uint4*)(trpb + a01));
    uint4 c2 = __ldg((const uint4*)(trpb + a10));
    uint4 c3 = __ldg((const uint4*)(trpb + a11));
    const unsigned* u0 = (const unsigned*)&c0;
    const unsigned* u1 = (const unsigned*)&c1;
    const unsigned* u2p = (const unsigned*)&c2;
    const unsigned* u3 = (const unsigned*)&c3;
#pragma unroll
    for (int k = 0; k < 4; k++) {
        __half2 v = __hmul2(w0, u2h(u0[k]));
        v = __hfma2(w1, u2h(u1[k]), v);
        v = __hfma2(w2, u2h(u2p[k]), v);
        v = __hfma2(w3, u2h(u3[k]), v);
        acc[k] = first ? v : __hmax2(acc[k], v);
    }
}

__global__ __launch_bounds__(THREADS, 7)
void crop_pool_kernel(const float* __restrict__ rois,
                      float* __restrict__ out)
{
    __shared__ int   sxi[2][PRE];  __shared__ float sxw[2][PRE];
    __shared__ int   syi[2][PRE];  __shared__ float syw[2][PRE];
    __shared__ uint4 srec[PRE * PRE];     // fused: cells u16x4 + 4 weights (half)
    __shared__ short s00tab[49];          // window -> first sample id
    __shared__ __align__(16) __half sout_h[NTASKS * SOUT_PAD];   // ~25.3KB

    const int roi    = blockIdx.x >> 1;
    const int chbase = (blockIdx.x & 1) * CHB;
    const int tid    = threadIdx.x;

    // ---- Phase 1: per-axis corner indices + weights (threads 0..27) ----
    if (tid < 2 * PRE) {
        const int isY = (tid >= PRE);
        const int j   = isY ? (tid - PRE) : tid;
        const float lo = rois[roi * 5 + (isY ? 2 : 1)] * (1.0f / 16.0f);
        const float hi = rois[roi * 5 + (isY ? 4 : 3)] * (1.0f / 16.0f);
        const float Lf = isY ? (float)(HH - 1) : (float)(WW - 1);
        const int   Li = isY ? (HH - 1) : (WW - 1);

        float ic = grid_coord(lo, hi, Lf, j);
        float f  = floorf(ic);
        float a  = ic - f;
        int i0 = (int)f;
        int i1 = i0 + 1;
        int i0c = min(max(i0, 0), Li);
        int i1c = min(max(i1, 0), Li);
        float w0 = (i0 >= 0 && i0 <= Li) ? (1.0f - a) : 0.0f;
        float w1 = (i1 >= 0 && i1 <= Li) ? a : 0.0f;

        if (!isY) {
            sxi[0][j] = i0c; sxi[1][j] = i1c; sxw[0][j] = w0; sxw[1][j] = w1;
        } else {
            syi[0][j] = i0c; syi[1][j] = i1c; syw[0][j] = w0; syw[1][j] = w1;
        }
    }
    // window -> s00 lookup (threads 32..80)
    if (tid >= 32 && tid < 32 + 49) {
        int win = tid - 32;
        int py = win / 7;
        int px = win - py * 7;
        s00tab[win] = (short)((2 * py) * PRE + 2 * px);
    }
    __syncthreads();

    // ---- Phase 2: fused per-sample records ----
#pragma unroll
    for (int sidb = 0; sidb < 2; sidb++) {
        int sid = tid + sidb * THREADS;
        if (sid < PRE * PRE) {
            const int jy = sid / PRE;
            const int jx = sid - jy * PRE;
            const int y0 = syi[0][jy], y1 = syi[1][jy];
            const int x0 = sxi[0][jx], x1 = sxi[1][jx];
            const float wy0 = syw[0][jy], wy1 = syw[1][jy];
            const float wx0 = sxw[0][jx], wx1 = sxw[1][jx];
            uint4 r;
            r.x = (unsigned)(y0 * WW + x0) | ((unsigned)(y0 * WW + x1) << 16);
            r.y = (unsigned)(y1 * WW + x0) | ((unsigned)(y1 * WW + x1) << 16);
            __half2 p01 = __floats2half2_rn(wy0 * wx0, wy0 * wx1);
            __half2 p23 = __floats2half2_rn(wy1 * wx0, wy1 * wx1);
            r.z = *(unsigned*)&p01;
            r.w = *(unsigned*)&p23;
            srec[sid] = r;
        }
    }
    __syncthreads();

    // PDL: wait for transpose grid's stores before reading g_trh
    asm volatile("griddepcontrol.wait;" ::: "memory");

    const int warp = tid >> 5;
    const int lane = tid & 31;

    // ---- Compute phase: 49 window-tasks, round-robin ----
    const int choff  = lane * 8;                       // local half-offset (16B/lane)
    const __half* __restrict__ trpb = g_trh + chbase + choff;

    for (int win = warp; win < NTASKS; win += NWARPS) {
        const int s00 = s00tab[win];
        __half2 m2[4];
#pragma unroll
        for (int s = 0; s < 4; s++) {
            const int sid = s00 + (s >> 1) * PRE + (s & 1);
            sample8(trpb, srec[sid], m2, s == 0);
        }
        *(uint4*)(&sout_h[win * SOUT_PAD + choff]) = *(uint4*)m2;
    }
    __syncthreads();

    // ---- Copy phase: shuffle-widened 128B main runs + parity-aware float2 tail ----
    const int oL    = lane & 15;
    const int halfp = lane >> 4;
    float* ob = out + (size_t)roi * (CCH * PS * PS) + (size_t)chbase * 49;

    for (int it = warp; it < CHB / 4; it += NWARPS) {
        const int c0 = it * 4;
        const __half* colbase = &sout_h[c0 + 2 * halfp];

        // main: o = 0..31 via two strided half2 reads + 2 shuffles
        unsigned a = *(const unsigned*)&colbase[(oL)      * SOUT_PAD];
        unsigned b = *(const unsigned*)&colbase[(oL + 16) * SOUT_PAD];
        unsigned ax = __shfl_xor_sync(0xffffffffu, a, 16);
        unsigned bx = __shfl_xor_sync(0xffffffffu, b, 16);
        unsigned p0 = (lane < 16) ? a  : bx;
        unsigned p1 = (lane < 16) ? ax : b;
        float2 f0 = __half22float2(u2h(p0));
        float2 f1 = __half22float2(u2h(p1));
        __stcs(&ob[(c0 + 0) * 49 + lane], f0.x);   // 128B contiguous run
        __stcs(&ob[(c0 + 1) * 49 + lane], f0.y);
        __stcs(&ob[(c0 + 2) * 49 + lane], f1.x);
        __stcs(&ob[(c0 + 3) * 49 + lane], f1.y);

        // tail: o = 32..48 as parity-aligned float2 runs (+1 scalar per channel).
        // Even channel (cq*49 even): float2 at o=32,34..46, scalar at o=48.
        // Odd channel  (cq*49 odd) : scalar at o=32, float2 at o=33,35..47 (covers 48).
        {
            const int q = lane >> 3;          // 0..3 -> channel c0+q
            const int i = lane & 7;           // pair index 0..7
            const int cq = c0 + q;
            const int oddc = cq & 1;
            const int o = (oddc ? 33 : 32) + 2 * i;
            const __half* colq = &sout_h[cq];
            __half h0 = colq[o * SOUT_PAD];
            __half h1 = colq[(o + 1) * SOUT_PAD];
            float2 fv = make_float2(__half2float(h0), __half2float(h1));
            *(float2*)&ob[cq * 49 + o] = fv;  // (cq*49 + o) is even -> 8B aligned
            if (i == 0) {
                const int os = oddc ? 32 : 48;
                __stcs(&ob[cq * 49 + os], __half2float(colq[os * SOUT_PAD]));
            }
        }
    }
}

extern "C" void kernel_launch(void* const* d_in, const int* in_sizes, int n_in,
                              void* d_out, int out_size)
{
    const float* bottom = (const float*)d_in[0];
    const float* rois   = (const float*)d_in[1];
    float* out = (float*)d_out;

    // transpose: 64-ch x 32-cell tiles
    dim3 tgrid((HWSZ + 31) / 32, CCH / 64);
    transpose_kernel<<<tgrid, dim3(32, 8)>>>(bottom);

    // crop kernel with PDL: setup overlaps the transpose tail.
    cudaLaunchConfig_t cfg = {};
    cfg.gridDim  = dim3(NROIS * 2, 1, 1);
    cfg.blockDim = dim3(THREADS, 1, 1);
    cfg.dynamicSmemBytes = 0;
    cfg.stream = 0;
    cudaLaunchAttribute attrs[1];
    attrs[0].id = cudaLaunchAttributeProgrammaticStreamSerialization;
    attrs[0].val.programmaticStreamSerializationAllowed = 1;
    cfg.attrs = attrs;
    cfg.numAttrs = 1;
    cudaLaunchKernelEx(&cfg, crop_pool_kernel, rois, out);
}

// round 16
// speedup vs baseline: 1.4257x; 1.0078x over previous
#include <cuda_runtime.h>
#include <cuda_fp16.h>

// Fixed problem shapes
#define NROIS 1024
#define CCH   512
#define HH    38
#define WW    50
#define HWSZ  (HH * WW)          // 1900
#define PRE   14                 // pooling_size * 2
#define PS    7

#define THREADS  128
#define NWARPS   (THREADS / 32)
#define NTASKS   49              // 49 windows (this CTA owns 256 channels)
#define CHB      256             // channels per CTA
#define SOUT_PAD 264             // halves per window row: 528B (16B-aligned), 2-way LDS max

// Transposed feature map in fp16: [cell = y*W + x][channel], 1.94 MB (L2-resident).
__device__ __align__(16) __half g_trh[HWSZ * CCH];

// ---------------- transpose+convert kernel: [C][H*W] fp32 -> [H*W][C] fp16 ----------------
__global__ __launch_bounds__(256)
void transpose_kernel(const float* __restrict__ bottom)
{
    __shared__ float t[64][33];
    const int c0 = blockIdx.x * 32;     // cell tile base
    const int h0 = blockIdx.y * 64;     // channel tile base
    const int tx = threadIdx.x;         // 0..31
    const int ty = threadIdx.y;         // 0..7

#pragma unroll
    for (int i = 0; i < 8; i++) {
        int ch = h0 + ty + i * 8;
        int cc = c0 + tx;
        t[ty + i * 8][tx] = (cc < HWSZ) ? bottom[ch * HWSZ + cc] : 0.0f;
    }
    __syncthreads();
#pragma unroll
    for (int i = 0; i < 4; i++) {
        int cc = c0 + ty + i * 8;
        if (cc < HWSZ) {
            __half2 v = __floats2half2_rn(t[2 * tx][ty + i * 8], t[2 * tx + 1][ty + i * 8]);
            *(__half2*)&g_trh[cc * CCH + h0 + 2 * tx] = v;
        }
    }
    asm volatile("griddepcontrol.launch_dependents;" ::: "memory");
}

// ---------------- main kernel: one CTA per (ROI, channel-half) ----------------
__device__ __forceinline__ float grid_coord(float lo, float hi, float L, int j) {
    float t0 = (hi - lo) / L;
    float t2 = (lo + hi - L) / L;
    float base = -1.0f + (float)j * (2.0f / 13.0f);
    float g = t0 * base + t2;
    return (g + 1.0f) * 0.5f * L;
}

// Per-axis bilinear params (identical arithmetic to previous rounds).
__device__ __forceinline__ void axis_params(float lo, float hi, int Li, int j,
                                            int& i0c, int& i1c, float& w0, float& w1)
{
    float ic = grid_coord(lo, hi, (float)Li, j);
    float f  = floorf(ic);
    float a  = ic - f;
    int i0 = (int)f;
    int i1 = i0 + 1;
    i0c = min(max(i0, 0), Li);
    i1c = min(max(i1, 0), Li);
    w0 = (i0 >= 0 && i0 <= Li) ? (1.0f - a) : 0.0f;
    w1 = (i1 >= 0 && i1 <= Li) ? a : 0.0f;
}

__device__ __forceinline__ __half2 u2h(unsigned u) { return *(__half2*)&u; }

// One bilinear sample for 8 channels (lane-local), given a fused record.
__device__ __forceinline__ void sample8(const __half* __restrict__ trpb,
                                        uint4 rec, __half2 acc[4], bool first)
{
    const __half2 p01 = u2h(rec.z);       // (w00, w01)
    const __half2 p23 = u2h(rec.w);       // (w10, w11)
    const __half2 w0 = __low2half2(p01), w1 = __high2half2(p01);
    const __half2 w2 = __low2half2(p23), w3 = __high2half2(p23);
    const int a00 = (int)(rec.x & 0xFFFFu) << 9;
    const int a01 = (int)(rec.x >> 16)     << 9;
    const int a10 = (int)(rec.y & 0xFFFFu) << 9;
    const int a11 = (int)(rec.y >> 16)     << 9;
    uint4 c0 = __ldg((const uint4*)(trpb + a00));
    uint4 c1 = __ldg((const uint4*)(trpb + a01));
    uint4 c2 = __ldg((const uint4*)(trpb + a10));
    uint4 c3 = __ldg((const uint4*)(trpb + a11));
    const unsigned* u0 = (const unsigned*)&c0;
    const unsigned* u1 = (const unsigned*)&c1;
    const unsigned* u2p = (const unsigned*)&c2;
    const unsigned* u3 = (const unsigned*)&c3;
#pragma unroll
    for (int k = 0; k < 4; k++) {
        __half2 v = __hmul2(w0, u2h(u0[k]));
        v = __hfma2(w1, u2h(u1[k]), v);
        v = __hfma2(w2, u2h(u2p[k]), v);
        v = __hfma2(w3, u2h(u3[k]), v);
        acc[k] = first ? v : __hmax2(acc[k], v);
    }
}

__global__ __launch_bounds__(THREADS, 7)
void crop_pool_kernel(const float* __restrict__ rois,
                      float* __restrict__ out)
{
    __shared__ uint4 srec[PRE * PRE];     // fused: cells u16x4 + 4 weights (half)
    __shared__ __align__(16) __half sout_h[NTASKS * SOUT_PAD];   // ~25.3KB

    const int roi    = blockIdx.x >> 1;
    const int chbase = (blockIdx.x & 1) * CHB;
    const int tid    = threadIdx.x;

    // ---- Single setup phase: each record thread computes its own axis math ----
#pragma unroll
    for (int sidb = 0; sidb < 2; sidb++) {
        int sid = tid + sidb * THREADS;
        if (sid < PRE * PRE) {
            const int jy = sid / PRE;
            const int jx = sid - jy * PRE;
            const float xlo = rois[roi * 5 + 1] * (1.0f / 16.0f);
            const float ylo = rois[roi * 5 + 2] * (1.0f / 16.0f);
            const float xhi = rois[roi * 5 + 3] * (1.0f / 16.0f);
            const float yhi = rois[roi * 5 + 4] * (1.0f / 16.0f);

            int x0, x1, y0, y1;
            float wx0, wx1, wy0, wy1;
            axis_params(xlo, xhi, WW - 1, jx, x0, x1, wx0, wx1);
            axis_params(ylo, yhi, HH - 1, jy, y0, y1, wy0, wy1);

            uint4 r;
            r.x = (unsigned)(y0 * WW + x0) | ((unsigned)(y0 * WW + x1) << 16);
            r.y = (unsigned)(y1 * WW + x0) | ((unsigned)(y1 * WW + x1) << 16);
            __half2 p01 = __floats2half2_rn(wy0 * wx0, wy0 * wx1);
            __half2 p23 = __floats2half2_rn(wy1 * wx0, wy1 * wx1);
            r.z = *(unsigned*)&p01;
            r.w = *(unsigned*)&p23;
            srec[sid] = r;
        }
    }
    __syncthreads();

    // PDL: wait for transpose grid's stores before reading g_trh
    asm volatile("griddepcontrol.wait;" ::: "memory");

    const int warp = tid >> 5;
    const int lane = tid & 31;

    // ---- Compute phase: 49 window-tasks, round-robin ----
    const int choff  = lane * 8;                       // local half-offset (16B/lane)
    const __half* __restrict__ trpb = g_trh + chbase + choff;

    for (int win = warp; win < NTASKS; win += NWARPS) {
        const int py  = win / 7;             // compiler: reciprocal-mul
        const int px  = win - py * 7;
        const int s00 = (2 * py) * PRE + 2 * px;
        __half2 m2[4];
#pragma unroll
        for (int s = 0; s < 4; s++) {
            const int sid = s00 + (s >> 1) * PRE + (s & 1);
            sample8(trpb, srec[sid], m2, s == 0);
        }
        *(uint4*)(&sout_h[win * SOUT_PAD + choff]) = *(uint4*)m2;
    }
    __syncthreads();

    // ---- Copy phase: shuffle-widened 128B main runs + parity-aware float2 tail ----
    const int oL    = lane & 15;
    const int halfp = lane >> 4;
    float* ob = out + (size_t)roi * (CCH * PS * PS) + (size_t)chbase * 49;

    for (int it = warp; it < CHB / 4; it += NWARPS) {
        const int c0 = it * 4;
        const __half* colbase = &sout_h[c0 + 2 * halfp];

        // main: o = 0..31 via two strided half2 reads + 2 shuffles
        unsigned a = *(const unsigned*)&colbase[(oL)      * SOUT_PAD];
        unsigned b = *(const unsigned*)&colbase[(oL + 16) * SOUT_PAD];
        unsigned ax = __shfl_xor_sync(0xffffffffu, a, 16);
        unsigned bx = __shfl_xor_sync(0xffffffffu, b, 16);
        unsigned p0 = (lane < 16) ? a  : bx;
        unsigned p1 = (lane < 16) ? ax : b;
        float2 f0 = __half22float2(u2h(p0));
        float2 f1 = __half22float2(u2h(p1));
        __stcs(&ob[(c0 + 0) * 49 + lane], f0.x);   // 128B contiguous run
        __stcs(&ob[(c0 + 1) * 49 + lane], f0.y);
        __stcs(&ob[(c0 + 2) * 49 + lane], f1.x);
        __stcs(&ob[(c0 + 3) * 49 + lane], f1.y);

        // tail: o = 32..48 as parity-aligned float2 runs (+1 scalar per channel).
        {
            const int q = lane >> 3;          // 0..3 -> channel c0+q
            const int i = lane & 7;           // pair index 0..7
            const int cq = c0 + q;
            const int oddc = cq & 1;
            const int o = (oddc ? 33 : 32) + 2 * i;
            const __half* colq = &sout_h[cq];
            __half h0 = colq[o * SOUT_PAD];
            __half h1 = colq[(o + 1) * SOUT_PAD];
            float2 fv = make_float2(__half2float(h0), __half2float(h1));
            *(float2*)&ob[cq * 49 + o] = fv;  // (cq*49 + o) is even -> 8B aligned
            if (i == 0) {
                const int os = oddc ? 32 : 48;
                __stcs(&ob[cq * 49 + os], __half2float(colq[os * SOUT_PAD]));
            }
        }
    }
}

extern "C" void kernel_launch(void* const* d_in, const int* in_sizes, int n_in,
                              void* d_out, int out_size)
{
    const float* bottom = (const float*)d_in[0];
    const float* rois   = (const float*)d_in[1];
    float* out = (float*)d_out;

    // transpose: 64-ch x 32-cell tiles
    dim3 tgrid((HWSZ + 31) / 32, CCH / 64);
    transpose_kernel<<<tgrid, dim3(32, 8)>>>(bottom);

    // crop kernel with PDL: setup overlaps the transpose tail.
    cudaLaunchConfig_t cfg = {};
    cfg.gridDim  = dim3(NROIS * 2, 1, 1);
    cfg.blockDim = dim3(THREADS, 1, 1);
    cfg.dynamicSmemBytes = 0;
    cfg.stream = 0;
    cudaLaunchAttribute attrs[1];
    attrs[0].id = cudaLaunchAttributeProgrammaticStreamSerialization;
    attrs[0].val.programmaticStreamSerializationAllowed = 1;
    cfg.attrs = attrs;
    cfg.numAttrs = 1;
    cudaLaunchKernelEx(&cfg, crop_pool_kernel, rois, out);
}